// round 13
// baseline (speedup 1.0000x reference)
#include <cuda_runtime.h>
#include <cuda_bf16.h>
#include <math.h>
#include <cstdint>

// Problem constants
#define NB 8
#define NT 1024
#define ND 512
#define NFF 2048
#define NH 8
#define NDH 64
#define MROWS (NB*NT)   // 8192

// ---------------- scratch (device globals; no allocation allowed) -----------
__device__ float g_qkv[(size_t)3*NB*NT*ND];          // (3,b,t,d)
__device__ float g_probs[(size_t)NB*NH*NT*NT];       // (b,h,q,k)  256 MB
__device__ float g_ctx[(size_t)NB*NT*ND];            // fp32 (w2 output)
__device__ float g_tmp[(size_t)NB*NT*NFF];           // fp32 (out-proj output)
__device__ float g_x1[(size_t)NB*NT*ND];
__device__ float g_outv[(size_t)NB*NT*ND];
__device__ float g_outl[(size_t)NB*NT*ND];
__device__ float g_colsum[NB*NT];
__device__ int   g_ids[NB*NT];
__device__ float g_wl[NB*NT];
// bf16 activation copies
__device__ __nv_bfloat16 g_ctxbf[(size_t)NB*NT*ND];
__device__ __nv_bfloat16 g_tmpbf[(size_t)NB*NT*NFF];
__device__ __nv_bfloat16 g_x1bf[(size_t)NB*NT*ND];
__device__ __nv_bfloat16 g_outvbf[(size_t)NB*NT*ND];
// transposed bf16 weights
__device__ __nv_bfloat16 g_wTbf[5505024];
// layer-1 qkv weights, transposed + tf32-split (hi/lo)
__device__ float g_wTqhi[3*ND*ND];
__device__ float g_wTqlo[3*ND*ND];
// layer-1 K plane, tf32-split
__device__ float g_khi[(size_t)NB*NT*ND];
__device__ float g_klo[(size_t)NB*NT*ND];

#define WT_VOUT 0
#define WT_VW1  (WT_VOUT + ND*ND)
#define WT_VW2  (WT_VW1 + NFF*ND)
#define WT_LQKV (WT_VW2 + ND*NFF)
#define WT_LOUT (WT_LQKV + 3*ND*ND)
#define WT_LW1  (WT_LOUT + ND*ND)
#define WT_LW2  (WT_LW1 + NFF*ND)

// ==================== small PTX helpers =====================================
__device__ __forceinline__ uint32_t smem_u32(const void* p) {
    uint32_t a;
    asm("{ .reg .u64 t; cvta.to.shared.u64 t, %1; cvt.u32.u64 %0, t; }" : "=r"(a) : "l"(p));
    return a;
}
__device__ __forceinline__ void cp_async16(uint32_t s, const void* g) {
    asm volatile("cp.async.cg.shared.global [%0], [%1], 16;" :: "r"(s), "l"(g));
}
__device__ __forceinline__ uint32_t tf32u(float x) {
    uint32_t u;
    asm("cvt.rna.tf32.f32 %0, %1;" : "=r"(u) : "f"(x));
    return u;
}
__device__ __forceinline__ float tf32r(float x) { return __uint_as_float(tf32u(x)); }
__device__ __forceinline__ uint32_t bf16pack(float lo, float hi) {
    uint32_t r;
    asm("cvt.rn.bf16x2.f32 %0, %1, %2;" : "=r"(r) : "f"(hi), "f"(lo));
    return r;
}
__device__ __forceinline__ void mma_tf32(float* d, const uint32_t* a, uint32_t b0, uint32_t b1) {
    asm volatile(
        "mma.sync.aligned.m16n8k8.row.col.f32.tf32.tf32.f32 "
        "{%0,%1,%2,%3}, {%4,%5,%6,%7}, {%8,%9}, {%0,%1,%2,%3};"
        : "+f"(d[0]), "+f"(d[1]), "+f"(d[2]), "+f"(d[3])
        : "r"(a[0]), "r"(a[1]), "r"(a[2]), "r"(a[3]), "r"(b0), "r"(b1));
}
__device__ __forceinline__ void mma_bf16(float* d, const uint32_t* a, uint32_t b0, uint32_t b1) {
    asm volatile(
        "mma.sync.aligned.m16n8k16.row.col.f32.bf16.bf16.f32 "
        "{%0,%1,%2,%3}, {%4,%5,%6,%7}, {%8,%9}, {%0,%1,%2,%3};"
        : "+f"(d[0]), "+f"(d[1]), "+f"(d[2]), "+f"(d[3])
        : "r"(a[0]), "r"(a[1]), "r"(a[2]), "r"(a[3]), "r"(b0), "r"(b1));
}

#define MMA_PITCH 20
#define TILE_F (128 * MMA_PITCH)                 // 2560 floats per tile buffer
#define SMEM_P0 (2 * 3 * TILE_F * 4)             // 61440  (A + B)
#define SMEM_P5 (3 * 3 * TILE_F * 4)             // 92160  (A + Bhi + Blo)

// =================== tf32 mma GEMM ==========================================
// C = A(MxK,lda) @ B(NxK,ldb)^T.
// EPI: 0 plain fp32; 2 scores (x0.125 + optional mask, z-batched over b,h);
//      4 fp32 + tf32-split dual planes (Chi/Clo).
// PREC: 0 = operands pre-rounded to tf32 (no cvt, 1 MMA);
//       5 = A runtime-split 3xTF32, B pre-split in (B, Blo_g) (3 MMAs, no B cvt).
template<int EPI, int PREC>
__global__ void __launch_bounds__(256) k_mma(const float* __restrict__ A,
                                             const float* __restrict__ B,
                                             const float* __restrict__ Blo_g,
                                             float* __restrict__ C,
                                             float* __restrict__ Chi,
                                             float* __restrict__ Clo,
                                             int N, int K, int lda, int ldb, int ldc,
                                             const int* __restrict__ ids) {
    extern __shared__ float dsm[];
    float* sA   = dsm;
    float* sB   = dsm + 3 * TILE_F;
    float* sBlo = dsm + 6 * TILE_F;   // valid only for PREC==5

    const int tid = threadIdx.x;
    const int wid = tid >> 5, lane = tid & 31;
    const int row0 = blockIdx.y * 128, col0 = blockIdx.x * 128;
    const int m_base = (wid & 3) * 32;
    const int n_base = (wid >> 2) * 64;
    const int g = lane >> 2, c = lane & 3;

    const float* Ap = A;
    const float* Bp = B;
    const float* Blop = Blo_g;
    float* Cp = C;
    const int* idb = nullptr;
    if (EPI == 2) {
        int bb = blockIdx.z >> 3, hh = blockIdx.z & 7;
        size_t off = (size_t)bb * NT * ND + hh * NDH;
        Ap = A + off; Bp = B + off;
        if (PREC == 5) Blop = Blo_g + off;
        Cp = C + (size_t)blockIdx.z * NT * NT;
        if (ids) idb = ids + bb * NT;
    }

    const uint32_t aS = smem_u32(sA);
    const uint32_t bS = smem_u32(sB);
    const uint32_t blS = smem_u32(sBlo);

    float acc[2][8][4];
    #pragma unroll
    for (int mt = 0; mt < 2; mt++)
        #pragma unroll
        for (int nt = 0; nt < 8; nt++)
            #pragma unroll
            for (int i = 0; i < 4; i++) acc[mt][nt][i] = 0.f;

    auto load_chunk = [&](int buf, int k0) {
        #pragma unroll
        for (int i = 0; i < 2; i++) {
            int q = tid + i * 256;
            int r = q >> 2, c4 = (q & 3) * 4;
            uint32_t soff = (uint32_t)((buf * TILE_F + r * MMA_PITCH + c4) * 4);
            cp_async16(aS + soff, Ap + (size_t)(row0 + r) * lda + k0 + c4);
            cp_async16(bS + soff, Bp + (size_t)(col0 + r) * ldb + k0 + c4);
            if (PREC == 5)
                cp_async16(blS + soff, Blop + (size_t)(col0 + r) * ldb + k0 + c4);
        }
        asm volatile("cp.async.commit_group;" ::: "memory");
    };

    const int nch = K >> 4;
    load_chunk(0, 0);
    if (nch > 1) load_chunk(1, 16);

    for (int ch = 0; ch < nch; ch++) {
        if (ch + 1 < nch) { asm volatile("cp.async.wait_group 1;" ::: "memory"); }
        else              { asm volatile("cp.async.wait_group 0;" ::: "memory"); }
        __syncthreads();
        if (ch + 2 < nch) load_chunk((ch + 2) % 3, (ch + 2) << 4);

        const float* pa  = sA + (ch % 3) * TILE_F;
        const float* pb  = sB + (ch % 3) * TILE_F;
        const float* pbl = sBlo + (ch % 3) * TILE_F;
        #pragma unroll
        for (int ks = 0; ks < 2; ks++) {
            const int k = ks * 8;
            uint32_t ahi[2][4], alo[2][4];
            #pragma unroll
            for (int mt = 0; mt < 2; mt++) {
                const float* ap = pa + (m_base + mt * 16 + g) * MMA_PITCH + k + c;
                float ar[4] = { ap[0], ap[8 * MMA_PITCH], ap[4], ap[8 * MMA_PITCH + 4] };
                #pragma unroll
                for (int j = 0; j < 4; j++) {
                    if (PREC == 0) {
                        ahi[mt][j] = __float_as_uint(ar[j]);   // pre-rounded
                    } else {
                        ahi[mt][j] = tf32u(ar[j]);
                        alo[mt][j] = tf32u(ar[j] - __uint_as_float(ahi[mt][j]));
                    }
                }
            }
            #pragma unroll
            for (int nt = 0; nt < 8; nt++) {
                const float* bp = pb + (n_base + nt * 8 + g) * MMA_PITCH + k + c;
                uint32_t bhi0 = __float_as_uint(bp[0]);
                uint32_t bhi1 = __float_as_uint(bp[4]);
                #pragma unroll
                for (int mt = 0; mt < 2; mt++) {
                    if (PREC == 5) {
                        const float* blp = pbl + (n_base + nt * 8 + g) * MMA_PITCH + k + c;
                        uint32_t blo0 = __float_as_uint(blp[0]);
                        uint32_t blo1 = __float_as_uint(blp[4]);
                        mma_tf32(acc[mt][nt], ahi[mt], blo0, blo1);
                        mma_tf32(acc[mt][nt], alo[mt], bhi0, bhi1);
                    }
                    mma_tf32(acc[mt][nt], ahi[mt], bhi0, bhi1);
                }
            }
        }
        __syncthreads();
    }

    #pragma unroll
    for (int mt = 0; mt < 2; mt++) {
        int r = row0 + m_base + mt * 16 + g;
        int iq0 = 0, iq1 = 0;
        if (EPI == 2 && idb) { iq0 = idb[r]; iq1 = idb[r + 8]; }
        #pragma unroll
        for (int nt = 0; nt < 8; nt++) {
            int cc = col0 + n_base + nt * 8 + 2 * c;
            float* d = acc[mt][nt];
            if (EPI == 2) {
                d[0] *= 0.125f; d[1] *= 0.125f; d[2] *= 0.125f; d[3] *= 0.125f;
                if (idb) {
                    int ik0 = idb[cc], ik1 = idb[cc + 1];
                    if (iq0 != ik0) d[0] = -1e30f;
                    if (iq0 != ik1) d[1] = -1e30f;
                    if (iq1 != ik0) d[2] = -1e30f;
                    if (iq1 != ik1) d[3] = -1e30f;
                }
            }
            *reinterpret_cast<float2*>(Cp + (size_t)r * ldc + cc)       = make_float2(d[0], d[1]);
            *reinterpret_cast<float2*>(Cp + (size_t)(r + 8) * ldc + cc) = make_float2(d[2], d[3]);
            if (EPI == 4) {
                float h0 = tf32r(d[0]), h1 = tf32r(d[1]), h2 = tf32r(d[2]), h3 = tf32r(d[3]);
                *reinterpret_cast<float2*>(Chi + (size_t)r * ldc + cc)       = make_float2(h0, h1);
                *reinterpret_cast<float2*>(Chi + (size_t)(r + 8) * ldc + cc) = make_float2(h2, h3);
                *reinterpret_cast<float2*>(Clo + (size_t)r * ldc + cc)       =
                    make_float2(tf32r(d[0] - h0), tf32r(d[1] - h1));
                *reinterpret_cast<float2*>(Clo + (size_t)(r + 8) * ldc + cc) =
                    make_float2(tf32r(d[2] - h2), tf32r(d[3] - h3));
            }
        }
    }
}

// =================== bf16 x bf16 mma GEMM (weight GEMMs) ====================
// C = A(MxK bf16,lda) @ Bt(NxK bf16,ldb)^T, m16n8k16, BK=16, 3-stage.
// EPI: 0 fp32 out, 2 relu + bf16 out, 3 tf32-rounded fp32 out.
#define BPITCH 12
template<int EPI>
__global__ void __launch_bounds__(256) k_mma_bb(const __nv_bfloat16* __restrict__ A,
                                                const __nv_bfloat16* __restrict__ Bt,
                                                void* __restrict__ Cv,
                                                int N, int K, int lda, int ldb, int ldc) {
    __shared__ uint32_t sA[3][128 * BPITCH];
    __shared__ uint32_t sB[3][128 * BPITCH];

    const int tid = threadIdx.x;
    const int wid = tid >> 5, lane = tid & 31;
    const int row0 = blockIdx.y * 128, col0 = blockIdx.x * 128;
    const int m_base = (wid & 3) * 32;
    const int n_base = (wid >> 2) * 64;
    const int g = lane >> 2, c = lane & 3;

    const uint32_t aS = smem_u32(sA);
    const uint32_t bS = smem_u32(sB);

    float acc[2][8][4];
    #pragma unroll
    for (int mt = 0; mt < 2; mt++)
        #pragma unroll
        for (int nt = 0; nt < 8; nt++)
            #pragma unroll
            for (int i = 0; i < 4; i++) acc[mt][nt][i] = 0.f;

    auto load_chunk = [&](int buf, int k0) {
        int r = tid >> 1, half = tid & 1;
        uint32_t soff = (uint32_t)((buf * 128 * BPITCH + r * BPITCH + half * 4) * 4);
        cp_async16(aS + soff, A + (size_t)(row0 + r) * lda + k0 + half * 8);
        cp_async16(bS + soff, Bt + (size_t)(col0 + r) * ldb + k0 + half * 8);
        asm volatile("cp.async.commit_group;" ::: "memory");
    };

    const int nch = K >> 4;
    load_chunk(0, 0);
    if (nch > 1) load_chunk(1, 16);

    for (int ch = 0; ch < nch; ch++) {
        if (ch + 1 < nch) { asm volatile("cp.async.wait_group 1;" ::: "memory"); }
        else              { asm volatile("cp.async.wait_group 0;" ::: "memory"); }
        __syncthreads();
        if (ch + 2 < nch) load_chunk((ch + 2) % 3, (ch + 2) << 4);

        const uint32_t* pa = sA[ch % 3];
        const uint32_t* pb = sB[ch % 3];

        uint32_t afr[2][4];
        #pragma unroll
        for (int mt = 0; mt < 2; mt++) {
            const uint32_t* ap = pa + (m_base + mt * 16 + g) * BPITCH + c;
            afr[mt][0] = ap[0];
            afr[mt][1] = ap[8 * BPITCH];
            afr[mt][2] = ap[4];
            afr[mt][3] = ap[8 * BPITCH + 4];
        }
        #pragma unroll
        for (int nt = 0; nt < 8; nt++) {
            const uint32_t* bp = pb + (n_base + nt * 8 + g) * BPITCH + c;
            uint32_t b0 = bp[0], b1 = bp[4];
            #pragma unroll
            for (int mt = 0; mt < 2; mt++)
                mma_bf16(acc[mt][nt], afr[mt], b0, b1);
        }
        __syncthreads();
    }

    #pragma unroll
    for (int mt = 0; mt < 2; mt++) {
        int r = row0 + m_base + mt * 16 + g;
        #pragma unroll
        for (int nt = 0; nt < 8; nt++) {
            int cc = col0 + n_base + nt * 8 + 2 * c;
            float* d = acc[mt][nt];
            if (EPI == 0) {
                float* C = (float*)Cv;
                *reinterpret_cast<float2*>(C + (size_t)r * ldc + cc)       = make_float2(d[0], d[1]);
                *reinterpret_cast<float2*>(C + (size_t)(r + 8) * ldc + cc) = make_float2(d[2], d[3]);
            } else if (EPI == 3) {
                float* C = (float*)Cv;
                *reinterpret_cast<float2*>(C + (size_t)r * ldc + cc)       =
                    make_float2(tf32r(d[0]), tf32r(d[1]));
                *reinterpret_cast<float2*>(C + (size_t)(r + 8) * ldc + cc) =
                    make_float2(tf32r(d[2]), tf32r(d[3]));
            } else {
                d[0] = fmaxf(d[0], 0.f); d[1] = fmaxf(d[1], 0.f);
                d[2] = fmaxf(d[2], 0.f); d[3] = fmaxf(d[3], 0.f);
                __nv_bfloat16* Cb = (__nv_bfloat16*)Cv;
                *reinterpret_cast<uint32_t*>(Cb + (size_t)r * ldc + cc)       = bf16pack(d[0], d[1]);
                *reinterpret_cast<uint32_t*>(Cb + (size_t)(r + 8) * ldc + cc) = bf16pack(d[2], d[3]);
            }
        }
    }
}

// =================== ctx mma: C[q,d] = sum_k P[q,k] V[k,d] (per b,h) ========
// bf16 output; colsum stays a separate coalesced kernel (R10 lesson).
#define VPITCH 72
__global__ void __launch_bounds__(256) k_mma_ctx(const float* __restrict__ P,
                                                 const float* __restrict__ qkv,
                                                 __nv_bfloat16* __restrict__ C) {
    __shared__ float sP[3][128 * MMA_PITCH];
    __shared__ float sV[3][16 * VPITCH];

    const int tid = threadIdx.x;
    const int wid = tid >> 5, lane = tid & 31;
    const int z = blockIdx.z;
    const int b = z >> 3, h = z & 7;
    const int row0 = blockIdx.x * 128;
    const int m_base = (wid & 3) * 32;
    const int n_base = (wid >> 2) * 32;
    const int g = lane >> 2, c = lane & 3;

    const float* Ap = P + (size_t)z * NT * NT;
    const float* Vp = qkv + (size_t)(2 * NB + b) * NT * ND + h * NDH;
    __nv_bfloat16* Cp = C + (size_t)b * NT * ND + h * NDH;

    const uint32_t pS = smem_u32(sP);
    const uint32_t vS = smem_u32(sV);

    float acc[2][4][4];
    #pragma unroll
    for (int mt = 0; mt < 2; mt++)
        #pragma unroll
        for (int nt = 0; nt < 4; nt++)
            #pragma unroll
            for (int i = 0; i < 4; i++) acc[mt][nt][i] = 0.f;

    auto load_chunk = [&](int buf, int k0) {
        #pragma unroll
        for (int i = 0; i < 2; i++) {
            int q = tid + i * 256;
            int r = q >> 2, c4 = (q & 3) * 4;
            uint32_t soff = (uint32_t)((buf * 128 * MMA_PITCH + r * MMA_PITCH + c4) * 4);
            cp_async16(pS + soff, Ap + (size_t)(row0 + r) * NT + k0 + c4);
        }
        {
            int r = tid >> 4, c4 = (tid & 15) * 4;
            uint32_t soff = (uint32_t)((buf * 16 * VPITCH + r * VPITCH + c4) * 4);
            cp_async16(vS + soff, Vp + (size_t)(k0 + r) * ND + c4);
        }
        asm volatile("cp.async.commit_group;" ::: "memory");
    };

    const int nch = NT >> 4;   // 64
    load_chunk(0, 0);
    load_chunk(1, 16);

    for (int ch = 0; ch < nch; ch++) {
        if (ch + 1 < nch) { asm volatile("cp.async.wait_group 1;" ::: "memory"); }
        else              { asm volatile("cp.async.wait_group 0;" ::: "memory"); }
        __syncthreads();
        if (ch + 2 < nch) load_chunk((ch + 2) % 3, (ch + 2) << 4);

        const float* pa = sP[ch % 3];
        const float* pv = sV[ch % 3];
        #pragma unroll
        for (int ks = 0; ks < 2; ks++) {
            const int k = ks * 8;
            uint32_t afr[2][4];
            #pragma unroll
            for (int mt = 0; mt < 2; mt++) {
                const float* ap = pa + (m_base + mt * 16 + g) * MMA_PITCH + k + c;
                afr[mt][0] = tf32u(ap[0]);
                afr[mt][1] = tf32u(ap[8 * MMA_PITCH]);
                afr[mt][2] = tf32u(ap[4]);
                afr[mt][3] = tf32u(ap[8 * MMA_PITCH + 4]);
            }
            #pragma unroll
            for (int nt = 0; nt < 4; nt++) {
                int n = n_base + nt * 8 + g;
                uint32_t b0 = tf32u(pv[(k + c) * VPITCH + n]);
                uint32_t b1 = tf32u(pv[(k + c + 4) * VPITCH + n]);
                #pragma unroll
                for (int mt = 0; mt < 2; mt++)
                    mma_tf32(acc[mt][nt], afr[mt], b0, b1);
            }
        }
        __syncthreads();
    }

    #pragma unroll
    for (int mt = 0; mt < 2; mt++) {
        int r = row0 + m_base + mt * 16 + g;
        #pragma unroll
        for (int nt = 0; nt < 4; nt++) {
            int cc = n_base + nt * 8 + 2 * c;
            float* d = acc[mt][nt];
            *reinterpret_cast<uint32_t*>(Cp + (size_t)r * ND + cc)       = bf16pack(d[0], d[1]);
            *reinterpret_cast<uint32_t*>(Cp + (size_t)(r + 8) * ND + cc) = bf16pack(d[2], d[3]);
        }
    }
}

// ---------------- weight transposes -----------------------------------------
__global__ void k_transpose_split(const float* __restrict__ B,
                                  float* __restrict__ Bhi, float* __restrict__ Blo,
                                  int K, int N) {
    __shared__ float t[32][33];
    int n0 = blockIdx.x * 32, k0 = blockIdx.y * 32;
    int tx = threadIdx.x, ty = threadIdx.y;
    #pragma unroll
    for (int i = 0; i < 4; i++)
        t[ty + i * 8][tx] = B[(size_t)(k0 + ty + i * 8) * N + n0 + tx];
    __syncthreads();
    #pragma unroll
    for (int i = 0; i < 4; i++) {
        float v = t[tx][ty + i * 8];
        float hi = tf32r(v);
        Bhi[(size_t)(n0 + ty + i * 8) * K + k0 + tx] = hi;
        Blo[(size_t)(n0 + ty + i * 8) * K + k0 + tx] = tf32r(v - hi);
    }
}

__global__ void k_transpose_bf16(const float* __restrict__ B, __nv_bfloat16* __restrict__ Bt,
                                 int K, int N) {
    __shared__ float t[32][33];
    int n0 = blockIdx.x * 32, k0 = blockIdx.y * 32;
    int tx = threadIdx.x, ty = threadIdx.y;
    #pragma unroll
    for (int i = 0; i < 4; i++)
        t[ty + i * 8][tx] = B[(size_t)(k0 + ty + i * 8) * N + n0 + tx];
    __syncthreads();
    #pragma unroll
    for (int i = 0; i < 4; i++)
        Bt[(size_t)(n0 + ty + i * 8) * K + k0 + tx] = __float2bfloat16(t[tx][ty + i * 8]);
}

// ---------------- row softmax over T=1024 (in place, vectorized) ------------
__global__ void k_softmax_rows(float* __restrict__ P) {
    size_t row = blockIdx.x;
    float4* p = reinterpret_cast<float4*>(P + row * (size_t)NT);
    __shared__ float red[256];
    int tid = threadIdx.x;
    float4 v = p[tid];
    float m = fmaxf(fmaxf(v.x, v.y), fmaxf(v.z, v.w));
    red[tid] = m; __syncthreads();
    for (int o = 128; o > 0; o >>= 1) { if (tid < o) red[tid] = fmaxf(red[tid], red[tid + o]); __syncthreads(); }
    m = red[0]; __syncthreads();
    v.x = __expf(v.x - m); v.y = __expf(v.y - m);
    v.z = __expf(v.z - m); v.w = __expf(v.w - m);
    red[tid] = v.x + v.y + v.z + v.w; __syncthreads();
    for (int o = 128; o > 0; o >>= 1) { if (tid < o) red[tid] += red[tid + o]; __syncthreads(); }
    float inv = 1.f / red[0];
    v.x *= inv; v.y *= inv; v.z *= inv; v.w *= inv;
    p[tid] = v;
}

__global__ void k_zero(float* p, int n) {
    int i = blockIdx.x * blockDim.x + threadIdx.x;
    if (i < n) p[i] = 0.f;
}

__global__ void k_colsum(const float* __restrict__ P, float* __restrict__ colsum) {
    int bh = blockIdx.y; int b = bh / NH;
    int k = blockIdx.x * 256 + threadIdx.x;
    const float* p = P + (size_t)bh * NT * NT + k;
    float acc = 0.f;
    #pragma unroll 8
    for (int q = 0; q < NT; q++) acc += p[(size_t)q * NT];
    atomicAdd(&colsum[b * NT + k], acc * (1.f / NH));
}

// ---------------- residual add + layernorm (dual fp32/bf16 output) ----------
__global__ void k_add_ln(const float* __restrict__ X, const float* __restrict__ Y,
                         float* __restrict__ O, __nv_bfloat16* __restrict__ Obf) {
    int row = blockIdx.x;
    const float* x = X + (size_t)row * ND;
    const float* y = Y + (size_t)row * ND;
    __shared__ float s[ND];
    __shared__ float red[256];
    int tid = threadIdx.x;
    float lsum = 0.f;
    for (int i = tid; i < ND; i += 256) { float v = x[i] + y[i]; s[i] = v; lsum += v; }
    red[tid] = lsum; __syncthreads();
    for (int o = 128; o > 0; o >>= 1) { if (tid < o) red[tid] += red[tid + o]; __syncthreads(); }
    float mean = red[0] * (1.f / ND); __syncthreads();
    float lv = 0.f;
    for (int i = tid; i < ND; i += 256) { float d = s[i] - mean; lv += d * d; }
    red[tid] = lv; __syncthreads();
    for (int o = 128; o > 0; o >>= 1) { if (tid < o) red[tid] += red[tid + o]; __syncthreads(); }
    float inv = rsqrtf(red[0] * (1.f / ND) + 1e-5f);
    for (int i = tid; i < ND; i += 256) {
        float v = (s[i] - mean) * inv;
        O[(size_t)row * ND + i] = v;
        if (Obf) Obf[(size_t)row * ND + i] = __float2bfloat16(v);
    }
}

// ---------------- window ids ------------------------------------------------
__global__ void k_windows(const float* __restrict__ colsum, int* __restrict__ ids) {
    int b = blockIdx.x;
    const float* w = colsum + b * NT;
    __shared__ float r1[256], r2[256];
    __shared__ unsigned char wb[NT];
    int tid = threadIdx.x;
    float mn = 1e30f, mx = -1e30f;
    for (int i = tid; i < NT; i += 256) { float v = w[i]; mn = fminf(mn, v); mx = fmaxf(mx, v); }
    r1[tid] = mn; r2[tid] = mx; __syncthreads();
    for (int o = 128; o > 0; o >>= 1) {
        if (tid < o) { r1[tid] = fminf(r1[tid], r1[tid + o]); r2[tid] = fmaxf(r2[tid], r2[tid + o]); }
        __syncthreads();
    }
    float wmin = r1[0];
    float denom = r2[0] - r1[0] + 1e-8f;
    for (int i = tid; i < NT; i += 256)
        wb[i] = ((w[i] - wmin) / denom >= 0.5f) ? 1 : 0;
    __syncthreads();
    if (tid == 0) {
        int* o = ids + b * NT;
        int cur = wb[0], start = 0, wid = 0;
        o[0] = 0;
        for (int t = 1; t < NT; t++) {
            int wt = wb[t];
            if (wt != cur) {
                if (start + 1 == t) { cur = wt; }
                else { cur = wt; start = t; wid++; }
            }
            o[t] = wid;
        }
    }
}

// ---------------- per-batch softmax over T (for wl) -------------------------
__global__ void k_softmax_vec(const float* __restrict__ in, float* __restrict__ out) {
    int b = blockIdx.x;
    const float* p = in + b * NT;
    float* q = out + b * NT;
    __shared__ float red[256];
    int tid = threadIdx.x;
    float v[4];
    float m = -1e30f;
    #pragma unroll
    for (int i = 0; i < 4; i++) { v[i] = p[tid + i * 256]; m = fmaxf(m, v[i]); }
    red[tid] = m; __syncthreads();
    for (int o = 128; o > 0; o >>= 1) { if (tid < o) red[tid] = fmaxf(red[tid], red[tid + o]); __syncthreads(); }
    m = red[0]; __syncthreads();
    float s = 0.f;
    #pragma unroll
    for (int i = 0; i < 4; i++) { v[i] = __expf(v[i] - m); s += v[i]; }
    red[tid] = s; __syncthreads();
    for (int o = 128; o > 0; o >>= 1) { if (tid < o) red[tid] += red[tid + o]; __syncthreads(); }
    float inv = 1.f / red[0];
    #pragma unroll
    for (int i = 0; i < 4; i++) q[tid + i * 256] = v[i] * inv;
}

// ---------------- output assembly -------------------------------------------
__global__ void k_out_base(const float* __restrict__ x, float* __restrict__ out) {
    size_t i = (size_t)blockIdx.x * blockDim.x + threadIdx.x;
    size_t total = (size_t)NB * 2 * NT * ND;
    if (i >= total) return;
    int d = (int)(i % ND);
    size_t r = i / ND;
    int row = (int)(r % (2 * NT));
    int b = (int)(r / (2 * NT));
    out[i] = (row < NT) ? 0.f : x[((size_t)b * NT + (row - NT)) * ND + d];
}

__global__ void k_scatter(const float* __restrict__ outl, const float* __restrict__ wl,
                          const int* __restrict__ ids, float* __restrict__ out) {
    int bt = blockIdx.x; int b = bt / NT;
    int w = ids[bt];
    float scale = wl[bt];
    float* dst = out + ((size_t)b * 2 * NT + w) * ND;
    const float* src = outl + (size_t)bt * ND;
    for (int d = threadIdx.x; d < ND; d += blockDim.x)
        atomicAdd(dst + d, src[d] * scale);
}

__global__ void k_winmap(const int* __restrict__ ids, float* __restrict__ out2) {
    size_t i = (size_t)blockIdx.x * blockDim.x + threadIdx.x;
    size_t total = (size_t)NB * NT * NT;
    if (i >= total) return;
    int t = (int)(i % NT);
    size_t r = i / NT;
    int w = (int)(r % NT);
    int b = (int)(r / NT);
    out2[i] = (ids[b * NT + t] == w) ? 1.f : 0.f;
}

// ---------------- host orchestration ----------------------------------------
template<int EPI, int PREC>
static inline void launch_mma(const float* A, const float* B, const float* Blo,
                              float* C, float* Chi, float* Clo,
                              int M, int N, int K, int lda, int ldb, int ldc,
                              const int* ids, int zdim) {
    const int smem = (PREC == 5) ? SMEM_P5 : SMEM_P0;
    static bool attr_done = false;
    if (!attr_done) {
        cudaFuncSetAttribute(k_mma<EPI, PREC>,
                             cudaFuncAttributeMaxDynamicSharedMemorySize, smem);
        attr_done = true;
    }
    dim3 grid(N / 128, M / 128, zdim);
    k_mma<EPI, PREC><<<grid, 256, smem>>>(A, B, Blo, C, Chi, Clo, N, K, lda, ldb, ldc, ids);
}

template<int EPI>
static inline void launch_bb(const __nv_bfloat16* A, const __nv_bfloat16* Bt, void* C,
                             int M, int N, int K, int lda, int ldb, int ldc) {
    dim3 grid(N / 128, M / 128);
    k_mma_bb<EPI><<<grid, 256>>>(A, Bt, C, N, K, lda, ldb, ldc);
}

extern "C" void kernel_launch(void* const* d_in, const int* in_sizes, int n_in,
                              void* d_out, int out_size) {
    const float* x      = (const float*)d_in[0];
    const float* v_qkvw = (const float*)d_in[1];
    const float* v_outw = (const float*)d_in[2];
    const float* v_w1   = (const float*)d_in[3];
    const float* v_w2   = (const float*)d_in[4];
    const float* l_qkvw = (const float*)d_in[5];
    const float* l_outw = (const float*)d_in[6];
    const float* l_w1   = (const float*)d_in[7];
    const float* l_w2   = (const float*)d_in[8];

    float *qkv, *probs, *ctx, *tmp, *x1, *outv, *outl, *colsum, *wl;
    float *wqhi, *wqlo, *khi, *klo;
    __nv_bfloat16 *wbf, *ctxbf, *tmpbf, *x1bf, *outvbf;
    int* ids;
    cudaGetSymbolAddress((void**)&qkv,    g_qkv);
    cudaGetSymbolAddress((void**)&probs,  g_probs);
    cudaGetSymbolAddress((void**)&ctx,    g_ctx);
    cudaGetSymbolAddress((void**)&tmp,    g_tmp);
    cudaGetSymbolAddress((void**)&x1,     g_x1);
    cudaGetSymbolAddress((void**)&outv,   g_outv);
    cudaGetSymbolAddress((void**)&outl,   g_outl);
    cudaGetSymbolAddress((void**)&colsum, g_colsum);
    cudaGetSymbolAddress((void**)&ids,    g_ids);
    cudaGetSymbolAddress((void**)&wl,     g_wl);
    cudaGetSymbolAddress((void**)&wbf,    g_wTbf);
    cudaGetSymbolAddress((void**)&wqhi,   g_wTqhi);
    cudaGetSymbolAddress((void**)&wqlo,   g_wTqlo);
    cudaGetSymbolAddress((void**)&khi,    g_khi);
    cudaGetSymbolAddress((void**)&klo,    g_klo);
    cudaGetSymbolAddress((void**)&ctxbf,  g_ctxbf);
    cudaGetSymbolAddress((void**)&tmpbf,  g_tmpbf);
    cudaGetSymbolAddress((void**)&x1bf,   g_x1bf);
    cudaGetSymbolAddress((void**)&outvbf, g_outvbf);

    float* out = (float*)d_out;
    size_t sz1 = (size_t)NB * 2 * NT * ND;
    size_t szwm = (size_t)NB * NT * NT;

    // ---- weight transposes ----
    dim3 tb(32, 8);
    for (int c = 0; c < 3; c++)
        k_transpose_split<<<dim3(ND / 32, ND / 32), tb>>>(v_qkvw + (size_t)c * ND * ND,
                                                          wqhi + (size_t)c * ND * ND,
                                                          wqlo + (size_t)c * ND * ND, ND, ND);
    k_transpose_bf16<<<dim3(ND / 32, ND / 32), tb>>>(v_outw, wbf + WT_VOUT, ND, ND);
    k_transpose_bf16<<<dim3(NFF / 32, ND / 32), tb>>>(v_w1, wbf + WT_VW1, ND, NFF);
    k_transpose_bf16<<<dim3(ND / 32, NFF / 32), tb>>>(v_w2, wbf + WT_VW2, NFF, ND);
    for (int c = 0; c < 3; c++)
        k_transpose_bf16<<<dim3(ND / 32, ND / 32), tb>>>(l_qkvw + (size_t)c * ND * ND,
                                                         wbf + WT_LQKV + (size_t)c * ND * ND, ND, ND);
    k_transpose_bf16<<<dim3(ND / 32, ND / 32), tb>>>(l_outw, wbf + WT_LOUT, ND, ND);
    k_transpose_bf16<<<dim3(NFF / 32, ND / 32), tb>>>(l_w1, wbf + WT_LW1, ND, NFF);
    k_transpose_bf16<<<dim3(ND / 32, NFF / 32), tb>>>(l_w2, wbf + WT_LW2, NFF, ND);

    // ---- Layer 1 (vanilla). Mask-critical path in 3xTF32 (B pre-split) ----
    // Q and V planes: plain fp32 out. K plane: fp32 + (hi,lo) tf32 planes.
    launch_mma<0, 5>(x, wqhi + 0 * ND * ND, wqlo + 0 * ND * ND,
                     qkv + 0 * (size_t)NB * NT * ND, nullptr, nullptr,
                     MROWS, ND, ND, ND, ND, ND, nullptr, 1);
    launch_mma<4, 5>(x, wqhi + 1 * ND * ND, wqlo + 1 * ND * ND,
                     qkv + 1 * (size_t)NB * NT * ND, khi, klo,
                     MROWS, ND, ND, ND, ND, ND, nullptr, 1);
    launch_mma<0, 5>(x, wqhi + 2 * ND * ND, wqlo + 2 * ND * ND,
                     qkv + 2 * (size_t)NB * NT * ND, nullptr, nullptr,
                     MROWS, ND, ND, ND, ND, ND, nullptr, 1);
    // scores: A = Q (runtime split), B = K pre-split planes
    launch_mma<2, 5>(qkv, khi, klo, probs, nullptr, nullptr,
                     NT, NT, NDH, ND, ND, NT, nullptr, NB * NH);
    k_softmax_rows<<<NB * NH * NT, 256>>>(probs);
    k_zero<<<(NB * NT + 255) / 256, 256>>>(colsum, NB * NT);
    k_colsum<<<dim3(NT / 256, NB * NH), 256>>>(probs, colsum);
    k_mma_ctx<<<dim3(NT / 128, 1, NB * NH), 256>>>(probs, qkv, ctxbf);
    launch_bb<0>(ctxbf, wbf + WT_VOUT, tmp, MROWS, ND, ND, ND, ND, ND);
    k_add_ln<<<MROWS, 256>>>(x, tmp, x1, x1bf);
    launch_bb<2>(x1bf, wbf + WT_VW1, tmpbf, MROWS, NFF, ND, ND, ND, NFF);
    launch_bb<0>(tmpbf, wbf + WT_VW2, ctx, MROWS, ND, NFF, NFF, NFF, ND);
    k_add_ln<<<MROWS, 256>>>(x1, ctx, outv, outvbf);

    // ---- window ids (inputs computed at ~fp32 accuracy) ----
    k_windows<<<NB, 256>>>(colsum, ids);

    // ---- Layer 2 (windowed mask). qkv tf32-pre-rounded -> scores need 0 cvt ----
    for (int c = 0; c < 3; c++)
        launch_bb<3>(outvbf, wbf + WT_LQKV + (size_t)c * ND * ND,
                     qkv + (size_t)c * NB * NT * ND, MROWS, ND, ND, ND, ND, ND);
    launch_mma<2, 0>(qkv, qkv + (size_t)NB * NT * ND, nullptr, probs, nullptr, nullptr,
                     NT, NT, NDH, ND, ND, NT, ids, NB * NH);
    k_softmax_rows<<<NB * NH * NT, 256>>>(probs);
    k_zero<<<(NB * NT + 255) / 256, 256>>>(colsum, NB * NT);
    k_colsum<<<dim3(NT / 256, NB * NH), 256>>>(probs, colsum);
    k_mma_ctx<<<dim3(NT / 128, 1, NB * NH), 256>>>(probs, qkv, ctxbf);
    launch_bb<0>(ctxbf, wbf + WT_LOUT, tmp, MROWS, ND, ND, ND, ND, ND);
    k_add_ln<<<MROWS, 256>>>(outv, tmp, x1, x1bf);
    launch_bb<2>(x1bf, wbf + WT_LW1, tmpbf, MROWS, NFF, ND, ND, ND, NFF);
    launch_bb<0>(tmpbf, wbf + WT_LW2, ctx, MROWS, ND, NFF, NFF, NFF, ND);
    k_add_ln<<<MROWS, 256>>>(x1, ctx, outl, nullptr);

    k_softmax_vec<<<NB, 256>>>(colsum, wl);

    // ---- Assemble outputs ----
    if ((size_t)out_size >= sz1) {
        k_out_base<<<(int)((sz1 + 255) / 256), 256>>>(x, out);
        k_scatter<<<NB * NT, 128>>>(outl, wl, ids, out);
    }
    if ((size_t)out_size >= sz1 + szwm) {
        k_winmap<<<(int)((szwm + 255) / 256), 256>>>(ids, out + sz1);
    }
}

// round 14
// speedup vs baseline: 1.7260x; 1.7260x over previous
#include <cuda_runtime.h>
#include <cuda_bf16.h>
#include <math.h>
#include <cstdint>

// Problem constants
#define NB 8
#define NT 1024
#define ND 512
#define NFF 2048
#define NH 8
#define NDH 64
#define MROWS (NB*NT)   // 8192

// ---------------- scratch (device globals; no allocation allowed) -----------
__device__ float g_qkv[(size_t)3*NB*NT*ND];          // (3,b,t,d)
__device__ float g_probs[(size_t)NB*NH*NT*NT];       // (b,h,q,k)  256 MB
__device__ float g_ctx[(size_t)NB*NT*ND];            // fp32 (w2 output)
__device__ float g_tmp[(size_t)NB*NT*NFF];           // fp32 (out-proj output)
__device__ float g_x1[(size_t)NB*NT*ND];
__device__ float g_outv[(size_t)NB*NT*ND];
__device__ float g_outl[(size_t)NB*NT*ND];
__device__ float g_colsum[NB*NT];
__device__ int   g_ids[NB*NT];
__device__ float g_wl[NB*NT];
// bf16 activation copies
__device__ __nv_bfloat16 g_ctxbf[(size_t)NB*NT*ND];
__device__ __nv_bfloat16 g_tmpbf[(size_t)NB*NT*NFF];
__device__ __nv_bfloat16 g_x1bf[(size_t)NB*NT*ND];
__device__ __nv_bfloat16 g_outvbf[(size_t)NB*NT*ND];
// transposed bf16 weights
__device__ __nv_bfloat16 g_wTbf[5505024];
// transposed raw fp32 layer-1 qkv weights for 3xTF32 GEMM
__device__ float g_wTq[3*ND*ND];

#define WT_VOUT 0
#define WT_VW1  (WT_VOUT + ND*ND)
#define WT_VW2  (WT_VW1 + NFF*ND)
#define WT_LQKV (WT_VW2 + ND*NFF)
#define WT_LOUT (WT_LQKV + 3*ND*ND)
#define WT_LW1  (WT_LOUT + ND*ND)
#define WT_LW2  (WT_LW1 + NFF*ND)

// ==================== small PTX helpers =====================================
__device__ __forceinline__ uint32_t smem_u32(const void* p) {
    uint32_t a;
    asm("{ .reg .u64 t; cvta.to.shared.u64 t, %1; cvt.u32.u64 %0, t; }" : "=r"(a) : "l"(p));
    return a;
}
__device__ __forceinline__ void cp_async16(uint32_t s, const void* g) {
    asm volatile("cp.async.cg.shared.global [%0], [%1], 16;" :: "r"(s), "l"(g));
}
__device__ __forceinline__ uint32_t tf32u(float x) {
    uint32_t u;
    asm("cvt.rna.tf32.f32 %0, %1;" : "=r"(u) : "f"(x));
    return u;
}
__device__ __forceinline__ uint32_t bf16pack(float lo, float hi) {
    uint32_t r;
    asm("cvt.rn.bf16x2.f32 %0, %1, %2;" : "=r"(r) : "f"(hi), "f"(lo));
    return r;
}
__device__ __forceinline__ void mma_tf32(float* d, const uint32_t* a, uint32_t b0, uint32_t b1) {
    asm volatile(
        "mma.sync.aligned.m16n8k8.row.col.f32.tf32.tf32.f32 "
        "{%0,%1,%2,%3}, {%4,%5,%6,%7}, {%8,%9}, {%0,%1,%2,%3};"
        : "+f"(d[0]), "+f"(d[1]), "+f"(d[2]), "+f"(d[3])
        : "r"(a[0]), "r"(a[1]), "r"(a[2]), "r"(a[3]), "r"(b0), "r"(b1));
}
__device__ __forceinline__ void mma_bf16(float* d, const uint32_t* a, uint32_t b0, uint32_t b1) {
    asm volatile(
        "mma.sync.aligned.m16n8k16.row.col.f32.bf16.bf16.f32 "
        "{%0,%1,%2,%3}, {%4,%5,%6,%7}, {%8,%9}, {%0,%1,%2,%3};"
        : "+f"(d[0]), "+f"(d[1]), "+f"(d[2]), "+f"(d[3])
        : "r"(a[0]), "r"(a[1]), "r"(a[2]), "r"(a[3]), "r"(b0), "r"(b1));
}

#define MMA_PITCH 20
#define MMA_SMEM_BYTES (2 * 3 * 128 * MMA_PITCH * 4)   // 61440

// =================== tf32 mma GEMM (scores + layer-1 qkv) ===================
// C = A(MxK,lda) @ B(NxK,ldb)^T.  EPI: 0 plain, 2 scores (x0.125 + mask, z-batched)
// PREC: 1 tf32, 3 = 3xTF32 split (fp32-comparable).
template<int EPI, int PREC>
__global__ void __launch_bounds__(256) k_mma(const float* __restrict__ A,
                                             const float* __restrict__ B,
                                             float* __restrict__ C,
                                             int N, int K, int lda, int ldb, int ldc,
                                             const int* __restrict__ ids) {
    extern __shared__ float dsm[];
    float* sA = dsm;
    float* sB = dsm + 3 * 128 * MMA_PITCH;

    const int tid = threadIdx.x;
    const int wid = tid >> 5, lane = tid & 31;
    const int row0 = blockIdx.y * 128, col0 = blockIdx.x * 128;
    const int m_base = (wid & 3) * 32;
    const int n_base = (wid >> 2) * 64;
    const int g = lane >> 2, c = lane & 3;

    const float* Ap = A;
    const float* Bp = B;
    float* Cp = C;
    const int* idb = nullptr;
    if (EPI == 2) {
        int bb = blockIdx.z >> 3, hh = blockIdx.z & 7;
        size_t off = (size_t)bb * NT * ND + hh * NDH;
        Ap = A + off; Bp = B + off;
        Cp = C + (size_t)blockIdx.z * NT * NT;
        if (ids) idb = ids + bb * NT;
    }

    const uint32_t aS = smem_u32(sA);
    const uint32_t bS = smem_u32(sB);

    float acc[2][8][4];
    #pragma unroll
    for (int mt = 0; mt < 2; mt++)
        #pragma unroll
        for (int nt = 0; nt < 8; nt++)
            #pragma unroll
            for (int i = 0; i < 4; i++) acc[mt][nt][i] = 0.f;

    auto load_chunk = [&](int buf, int k0) {
        #pragma unroll
        for (int i = 0; i < 2; i++) {
            int q = tid + i * 256;
            int r = q >> 2, c4 = (q & 3) * 4;
            uint32_t soff = (uint32_t)((buf * 128 * MMA_PITCH + r * MMA_PITCH + c4) * 4);
            cp_async16(aS + soff, Ap + (size_t)(row0 + r) * lda + k0 + c4);
            cp_async16(bS + soff, Bp + (size_t)(col0 + r) * ldb + k0 + c4);
        }
        asm volatile("cp.async.commit_group;" ::: "memory");
    };

    const int nch = K >> 4;
    load_chunk(0, 0);
    if (nch > 1) load_chunk(1, 16);

    for (int ch = 0; ch < nch; ch++) {
        if (ch + 1 < nch) { asm volatile("cp.async.wait_group 1;" ::: "memory"); }
        else              { asm volatile("cp.async.wait_group 0;" ::: "memory"); }
        __syncthreads();
        if (ch + 2 < nch) load_chunk((ch + 2) % 3, (ch + 2) << 4);

        const float* pa = sA + (ch % 3) * 128 * MMA_PITCH;
        const float* pb = sB + (ch % 3) * 128 * MMA_PITCH;
        #pragma unroll
        for (int ks = 0; ks < 2; ks++) {
            const int k = ks * 8;
            uint32_t ahi[2][4], alo[2][4];
            #pragma unroll
            for (int mt = 0; mt < 2; mt++) {
                const float* ap = pa + (m_base + mt * 16 + g) * MMA_PITCH + k + c;
                float ar[4] = { ap[0], ap[8 * MMA_PITCH], ap[4], ap[8 * MMA_PITCH + 4] };
                #pragma unroll
                for (int j = 0; j < 4; j++) {
                    ahi[mt][j] = tf32u(ar[j]);
                    if (PREC == 3)
                        alo[mt][j] = tf32u(ar[j] - __uint_as_float(ahi[mt][j]));
                }
            }
            #pragma unroll
            for (int nt = 0; nt < 8; nt++) {
                const float* bp = pb + (n_base + nt * 8 + g) * MMA_PITCH + k + c;
                float br0 = bp[0], br1 = bp[4];
                uint32_t bhi0 = tf32u(br0), bhi1 = tf32u(br1);
                uint32_t blo0 = 0, blo1 = 0;
                if (PREC == 3) {
                    blo0 = tf32u(br0 - __uint_as_float(bhi0));
                    blo1 = tf32u(br1 - __uint_as_float(bhi1));
                }
                #pragma unroll
                for (int mt = 0; mt < 2; mt++) {
                    if (PREC == 3) {
                        mma_tf32(acc[mt][nt], ahi[mt], blo0, blo1);
                        mma_tf32(acc[mt][nt], alo[mt], bhi0, bhi1);
                    }
                    mma_tf32(acc[mt][nt], ahi[mt], bhi0, bhi1);
                }
            }
        }
        __syncthreads();
    }

    #pragma unroll
    for (int mt = 0; mt < 2; mt++) {
        int r = row0 + m_base + mt * 16 + g;
        int iq0 = 0, iq1 = 0;
        if (EPI == 2 && idb) { iq0 = idb[r]; iq1 = idb[r + 8]; }
        #pragma unroll
        for (int nt = 0; nt < 8; nt++) {
            int cc = col0 + n_base + nt * 8 + 2 * c;
            float* d = acc[mt][nt];
            if (EPI == 2) {
                d[0] *= 0.125f; d[1] *= 0.125f; d[2] *= 0.125f; d[3] *= 0.125f;
                if (idb) {
                    int ik0 = idb[cc], ik1 = idb[cc + 1];
                    if (iq0 != ik0) d[0] = -1e30f;
                    if (iq0 != ik1) d[1] = -1e30f;
                    if (iq1 != ik0) d[2] = -1e30f;
                    if (iq1 != ik1) d[3] = -1e30f;
                }
            }
            *reinterpret_cast<float2*>(Cp + (size_t)r * ldc + cc)       = make_float2(d[0], d[1]);
            *reinterpret_cast<float2*>(Cp + (size_t)(r + 8) * ldc + cc) = make_float2(d[2], d[3]);
        }
    }
}

// =================== bf16 x bf16 mma GEMM (weight GEMMs) ====================
// C = A(MxK bf16,lda) @ Bt(NxK bf16,ldb)^T, m16n8k16, BK=16, 3-stage.
// EPI: 0 fp32 out, 2 relu + bf16 out.
#define BPITCH 12
template<int EPI>
__global__ void __launch_bounds__(256) k_mma_bb(const __nv_bfloat16* __restrict__ A,
                                                const __nv_bfloat16* __restrict__ Bt,
                                                void* __restrict__ Cv,
                                                int N, int K, int lda, int ldb, int ldc) {
    __shared__ uint32_t sA[3][128 * BPITCH];
    __shared__ uint32_t sB[3][128 * BPITCH];

    const int tid = threadIdx.x;
    const int wid = tid >> 5, lane = tid & 31;
    const int row0 = blockIdx.y * 128, col0 = blockIdx.x * 128;
    const int m_base = (wid & 3) * 32;
    const int n_base = (wid >> 2) * 64;
    const int g = lane >> 2, c = lane & 3;

    const uint32_t aS = smem_u32(sA);
    const uint32_t bS = smem_u32(sB);

    float acc[2][8][4];
    #pragma unroll
    for (int mt = 0; mt < 2; mt++)
        #pragma unroll
        for (int nt = 0; nt < 8; nt++)
            #pragma unroll
            for (int i = 0; i < 4; i++) acc[mt][nt][i] = 0.f;

    auto load_chunk = [&](int buf, int k0) {
        int r = tid >> 1, half = tid & 1;
        uint32_t soff = (uint32_t)((buf * 128 * BPITCH + r * BPITCH + half * 4) * 4);
        cp_async16(aS + soff, A + (size_t)(row0 + r) * lda + k0 + half * 8);
        cp_async16(bS + soff, Bt + (size_t)(col0 + r) * ldb + k0 + half * 8);
        asm volatile("cp.async.commit_group;" ::: "memory");
    };

    const int nch = K >> 4;
    load_chunk(0, 0);
    if (nch > 1) load_chunk(1, 16);

    for (int ch = 0; ch < nch; ch++) {
        if (ch + 1 < nch) { asm volatile("cp.async.wait_group 1;" ::: "memory"); }
        else              { asm volatile("cp.async.wait_group 0;" ::: "memory"); }
        __syncthreads();
        if (ch + 2 < nch) load_chunk((ch + 2) % 3, (ch + 2) << 4);

        const uint32_t* pa = sA[ch % 3];
        const uint32_t* pb = sB[ch % 3];

        uint32_t afr[2][4];
        #pragma unroll
        for (int mt = 0; mt < 2; mt++) {
            const uint32_t* ap = pa + (m_base + mt * 16 + g) * BPITCH + c;
            afr[mt][0] = ap[0];
            afr[mt][1] = ap[8 * BPITCH];
            afr[mt][2] = ap[4];
            afr[mt][3] = ap[8 * BPITCH + 4];
        }
        #pragma unroll
        for (int nt = 0; nt < 8; nt++) {
            const uint32_t* bp = pb + (n_base + nt * 8 + g) * BPITCH + c;
            uint32_t b0 = bp[0], b1 = bp[4];
            #pragma unroll
            for (int mt = 0; mt < 2; mt++)
                mma_bf16(acc[mt][nt], afr[mt], b0, b1);
        }
        __syncthreads();
    }

    #pragma unroll
    for (int mt = 0; mt < 2; mt++) {
        int r = row0 + m_base + mt * 16 + g;
        #pragma unroll
        for (int nt = 0; nt < 8; nt++) {
            int cc = col0 + n_base + nt * 8 + 2 * c;
            float* d = acc[mt][nt];
            if (EPI == 0) {
                float* C = (float*)Cv;
                *reinterpret_cast<float2*>(C + (size_t)r * ldc + cc)       = make_float2(d[0], d[1]);
                *reinterpret_cast<float2*>(C + (size_t)(r + 8) * ldc + cc) = make_float2(d[2], d[3]);
            } else {
                d[0] = fmaxf(d[0], 0.f); d[1] = fmaxf(d[1], 0.f);
                d[2] = fmaxf(d[2], 0.f); d[3] = fmaxf(d[3], 0.f);
                __nv_bfloat16* Cb = (__nv_bfloat16*)Cv;
                *reinterpret_cast<uint32_t*>(Cb + (size_t)r * ldc + cc)       = bf16pack(d[0], d[1]);
                *reinterpret_cast<uint32_t*>(Cb + (size_t)(r + 8) * ldc + cc) = bf16pack(d[2], d[3]);
            }
        }
    }
}

// =================== ctx mma: C[q,d] = sum_k P[q,k] V[k,d] (per b,h) ========
// bf16 output; colsum handled in the fused softmax kernel.
#define VPITCH 72
__global__ void __launch_bounds__(256) k_mma_ctx(const float* __restrict__ P,
                                                 const float* __restrict__ qkv,
                                                 __nv_bfloat16* __restrict__ C) {
    __shared__ float sP[3][128 * MMA_PITCH];
    __shared__ float sV[3][16 * VPITCH];

    const int tid = threadIdx.x;
    const int wid = tid >> 5, lane = tid & 31;
    const int z = blockIdx.z;
    const int b = z >> 3, h = z & 7;
    const int row0 = blockIdx.x * 128;
    const int m_base = (wid & 3) * 32;
    const int n_base = (wid >> 2) * 32;
    const int g = lane >> 2, c = lane & 3;

    const float* Ap = P + (size_t)z * NT * NT;
    const float* Vp = qkv + (size_t)(2 * NB + b) * NT * ND + h * NDH;
    __nv_bfloat16* Cp = C + (size_t)b * NT * ND + h * NDH;

    const uint32_t pS = smem_u32(sP);
    const uint32_t vS = smem_u32(sV);

    float acc[2][4][4];
    #pragma unroll
    for (int mt = 0; mt < 2; mt++)
        #pragma unroll
        for (int nt = 0; nt < 4; nt++)
            #pragma unroll
            for (int i = 0; i < 4; i++) acc[mt][nt][i] = 0.f;

    auto load_chunk = [&](int buf, int k0) {
        #pragma unroll
        for (int i = 0; i < 2; i++) {
            int q = tid + i * 256;
            int r = q >> 2, c4 = (q & 3) * 4;
            uint32_t soff = (uint32_t)((buf * 128 * MMA_PITCH + r * MMA_PITCH + c4) * 4);
            cp_async16(pS + soff, Ap + (size_t)(row0 + r) * NT + k0 + c4);
        }
        {
            int r = tid >> 4, c4 = (tid & 15) * 4;
            uint32_t soff = (uint32_t)((buf * 16 * VPITCH + r * VPITCH + c4) * 4);
            cp_async16(vS + soff, Vp + (size_t)(k0 + r) * ND + c4);
        }
        asm volatile("cp.async.commit_group;" ::: "memory");
    };

    const int nch = NT >> 4;   // 64
    load_chunk(0, 0);
    load_chunk(1, 16);

    for (int ch = 0; ch < nch; ch++) {
        if (ch + 1 < nch) { asm volatile("cp.async.wait_group 1;" ::: "memory"); }
        else              { asm volatile("cp.async.wait_group 0;" ::: "memory"); }
        __syncthreads();
        if (ch + 2 < nch) load_chunk((ch + 2) % 3, (ch + 2) << 4);

        const float* pa = sP[ch % 3];
        const float* pv = sV[ch % 3];
        #pragma unroll
        for (int ks = 0; ks < 2; ks++) {
            const int k = ks * 8;
            uint32_t afr[2][4];
            #pragma unroll
            for (int mt = 0; mt < 2; mt++) {
                const float* ap = pa + (m_base + mt * 16 + g) * MMA_PITCH + k + c;
                afr[mt][0] = tf32u(ap[0]);
                afr[mt][1] = tf32u(ap[8 * MMA_PITCH]);
                afr[mt][2] = tf32u(ap[4]);
                afr[mt][3] = tf32u(ap[8 * MMA_PITCH + 4]);
            }
            #pragma unroll
            for (int nt = 0; nt < 4; nt++) {
                int n = n_base + nt * 8 + g;
                uint32_t b0 = tf32u(pv[(k + c) * VPITCH + n]);
                uint32_t b1 = tf32u(pv[(k + c + 4) * VPITCH + n]);
                #pragma unroll
                for (int mt = 0; mt < 2; mt++)
                    mma_tf32(acc[mt][nt], afr[mt], b0, b1);
            }
        }
        __syncthreads();
    }

    #pragma unroll
    for (int mt = 0; mt < 2; mt++) {
        int r = row0 + m_base + mt * 16 + g;
        #pragma unroll
        for (int nt = 0; nt < 4; nt++) {
            int cc = n_base + nt * 8 + 2 * c;
            float* d = acc[mt][nt];
            *reinterpret_cast<uint32_t*>(Cp + (size_t)r * ND + cc)       = bf16pack(d[0], d[1]);
            *reinterpret_cast<uint32_t*>(Cp + (size_t)(r + 8) * ND + cc) = bf16pack(d[2], d[3]);
        }
    }
}

// ---------------- weight transposes -----------------------------------------
__global__ void k_transpose(const float* __restrict__ B, float* __restrict__ Bt,
                            int K, int N) {
    __shared__ float t[32][33];
    int n0 = blockIdx.x * 32, k0 = blockIdx.y * 32;
    int tx = threadIdx.x, ty = threadIdx.y;
    #pragma unroll
    for (int i = 0; i < 4; i++)
        t[ty + i * 8][tx] = B[(size_t)(k0 + ty + i * 8) * N + n0 + tx];
    __syncthreads();
    #pragma unroll
    for (int i = 0; i < 4; i++)
        Bt[(size_t)(n0 + ty + i * 8) * K + k0 + tx] = t[tx][ty + i * 8];
}

__global__ void k_transpose_bf16(const float* __restrict__ B, __nv_bfloat16* __restrict__ Bt,
                                 int K, int N) {
    __shared__ float t[32][33];
    int n0 = blockIdx.x * 32, k0 = blockIdx.y * 32;
    int tx = threadIdx.x, ty = threadIdx.y;
    #pragma unroll
    for (int i = 0; i < 4; i++)
        t[ty + i * 8][tx] = B[(size_t)(k0 + ty + i * 8) * N + n0 + tx];
    __syncthreads();
    #pragma unroll
    for (int i = 0; i < 4; i++)
        Bt[(size_t)(n0 + ty + i * 8) * K + k0 + tx] = __float2bfloat16(t[tx][ty + i * 8]);
}

// ---------- fused row softmax + colsum over 16 rows per CTA ------------------
// grid: (NT/16, NB*NH), block 256 (8 warps, 2 rows each).
// Row path is warp-shuffle only (no block barriers); column partials are kept
// in registers, merged via spread-address smem atomics once per block, then one
// global atomicAdd sweep (512 updates per colsum address in total).
__global__ void __launch_bounds__(256) k_softmax_colsum(float* __restrict__ P,
                                                        float* __restrict__ colsum) {
    const int z = blockIdx.y;
    const int b = z >> 3;
    const int row0 = blockIdx.x * 16;
    const int tid = threadIdx.x;
    const int wid = tid >> 5, lane = tid & 31;

    __shared__ float scol[NT];
    for (int i = tid; i < NT; i += 256) scol[i] = 0.f;
    __syncthreads();

    float4 accc[8];
    #pragma unroll
    for (int j = 0; j < 8; j++) accc[j] = make_float4(0.f, 0.f, 0.f, 0.f);

    #pragma unroll
    for (int rr = 0; rr < 2; rr++) {
        int r = row0 + wid * 2 + rr;
        float4* p = reinterpret_cast<float4*>(P + ((size_t)z * NT + r) * NT);
        float4 v[8];
        float m = -1e30f;
        #pragma unroll
        for (int j = 0; j < 8; j++) {
            v[j] = p[j * 32 + lane];
            m = fmaxf(m, fmaxf(fmaxf(v[j].x, v[j].y), fmaxf(v[j].z, v[j].w)));
        }
        #pragma unroll
        for (int o = 16; o > 0; o >>= 1) m = fmaxf(m, __shfl_xor_sync(0xFFFFFFFFu, m, o));
        float s = 0.f;
        #pragma unroll
        for (int j = 0; j < 8; j++) {
            v[j].x = __expf(v[j].x - m); v[j].y = __expf(v[j].y - m);
            v[j].z = __expf(v[j].z - m); v[j].w = __expf(v[j].w - m);
            s += v[j].x + v[j].y + v[j].z + v[j].w;
        }
        #pragma unroll
        for (int o = 16; o > 0; o >>= 1) s += __shfl_xor_sync(0xFFFFFFFFu, s, o);
        float inv = 1.f / s;
        #pragma unroll
        for (int j = 0; j < 8; j++) {
            v[j].x *= inv; v[j].y *= inv; v[j].z *= inv; v[j].w *= inv;
            p[j * 32 + lane] = v[j];
            accc[j].x += v[j].x; accc[j].y += v[j].y;
            accc[j].z += v[j].z; accc[j].w += v[j].w;
        }
    }

    // merge per-lane column partials (cols (j*32+lane)*4 + 0..3) into smem
    #pragma unroll
    for (int j = 0; j < 8; j++) {
        int cb = (j * 32 + lane) * 4;
        atomicAdd(&scol[cb + 0], accc[j].x);
        atomicAdd(&scol[cb + 1], accc[j].y);
        atomicAdd(&scol[cb + 2], accc[j].z);
        atomicAdd(&scol[cb + 3], accc[j].w);
    }
    __syncthreads();
    for (int i = tid; i < NT; i += 256)
        atomicAdd(&colsum[b * NT + i], scol[i] * (1.f / NH));
}

__global__ void k_zero(float* p, int n) {
    int i = blockIdx.x * blockDim.x + threadIdx.x;
    if (i < n) p[i] = 0.f;
}

// ---------------- residual add + layernorm (dual fp32/bf16 output) ----------
__global__ void k_add_ln(const float* __restrict__ X, const float* __restrict__ Y,
                         float* __restrict__ O, __nv_bfloat16* __restrict__ Obf) {
    int row = blockIdx.x;
    const float* x = X + (size_t)row * ND;
    const float* y = Y + (size_t)row * ND;
    __shared__ float s[ND];
    __shared__ float red[256];
    int tid = threadIdx.x;
    float lsum = 0.f;
    for (int i = tid; i < ND; i += 256) { float v = x[i] + y[i]; s[i] = v; lsum += v; }
    red[tid] = lsum; __syncthreads();
    for (int o = 128; o > 0; o >>= 1) { if (tid < o) red[tid] += red[tid + o]; __syncthreads(); }
    float mean = red[0] * (1.f / ND); __syncthreads();
    float lv = 0.f;
    for (int i = tid; i < ND; i += 256) { float d = s[i] - mean; lv += d * d; }
    red[tid] = lv; __syncthreads();
    for (int o = 128; o > 0; o >>= 1) { if (tid < o) red[tid] += red[tid + o]; __syncthreads(); }
    float inv = rsqrtf(red[0] * (1.f / ND) + 1e-5f);
    for (int i = tid; i < ND; i += 256) {
        float v = (s[i] - mean) * inv;
        O[(size_t)row * ND + i] = v;
        if (Obf) Obf[(size_t)row * ND + i] = __float2bfloat16(v);
    }
}

// ---------------- window ids ------------------------------------------------
__global__ void k_windows(const float* __restrict__ colsum, int* __restrict__ ids) {
    int b = blockIdx.x;
    const float* w = colsum + b * NT;
    __shared__ float r1[256], r2[256];
    __shared__ unsigned char wb[NT];
    int tid = threadIdx.x;
    float mn = 1e30f, mx = -1e30f;
    for (int i = tid; i < NT; i += 256) { float v = w[i]; mn = fminf(mn, v); mx = fmaxf(mx, v); }
    r1[tid] = mn; r2[tid] = mx; __syncthreads();
    for (int o = 128; o > 0; o >>= 1) {
        if (tid < o) { r1[tid] = fminf(r1[tid], r1[tid + o]); r2[tid] = fmaxf(r2[tid], r2[tid + o]); }
        __syncthreads();
    }
    float wmin = r1[0];
    float denom = r2[0] - r1[0] + 1e-8f;
    for (int i = tid; i < NT; i += 256)
        wb[i] = ((w[i] - wmin) / denom >= 0.5f) ? 1 : 0;
    __syncthreads();
    if (tid == 0) {
        int* o = ids + b * NT;
        int cur = wb[0], start = 0, wid = 0;
        o[0] = 0;
        for (int t = 1; t < NT; t++) {
            int wt = wb[t];
            if (wt != cur) {
                if (start + 1 == t) { cur = wt; }
                else { cur = wt; start = t; wid++; }
            }
            o[t] = wid;
        }
    }
}

// ---------------- per-batch softmax over T (for wl) -------------------------
__global__ void k_softmax_vec(const float* __restrict__ in, float* __restrict__ out) {
    int b = blockIdx.x;
    const float* p = in + b * NT;
    float* q = out + b * NT;
    __shared__ float red[256];
    int tid = threadIdx.x;
    float v[4];
    float m = -1e30f;
    #pragma unroll
    for (int i = 0; i < 4; i++) { v[i] = p[tid + i * 256]; m = fmaxf(m, v[i]); }
    red[tid] = m; __syncthreads();
    for (int o = 128; o > 0; o >>= 1) { if (tid < o) red[tid] = fmaxf(red[tid], red[tid + o]); __syncthreads(); }
    m = red[0]; __syncthreads();
    float s = 0.f;
    #pragma unroll
    for (int i = 0; i < 4; i++) { v[i] = __expf(v[i] - m); s += v[i]; }
    red[tid] = s; __syncthreads();
    for (int o = 128; o > 0; o >>= 1) { if (tid < o) red[tid] += red[tid + o]; __syncthreads(); }
    float inv = 1.f / red[0];
    #pragma unroll
    for (int i = 0; i < 4; i++) q[tid + i * 256] = v[i] * inv;
}

// ---------------- output assembly -------------------------------------------
__global__ void k_out_base(const float* __restrict__ x, float* __restrict__ out) {
    size_t i = (size_t)blockIdx.x * blockDim.x + threadIdx.x;
    size_t total = (size_t)NB * 2 * NT * ND;
    if (i >= total) return;
    int d = (int)(i % ND);
    size_t r = i / ND;
    int row = (int)(r % (2 * NT));
    int b = (int)(r / (2 * NT));
    out[i] = (row < NT) ? 0.f : x[((size_t)b * NT + (row - NT)) * ND + d];
}

__global__ void k_scatter(const float* __restrict__ outl, const float* __restrict__ wl,
                          const int* __restrict__ ids, float* __restrict__ out) {
    int bt = blockIdx.x; int b = bt / NT;
    int w = ids[bt];
    float scale = wl[bt];
    float* dst = out + ((size_t)b * 2 * NT + w) * ND;
    const float* src = outl + (size_t)bt * ND;
    for (int d = threadIdx.x; d < ND; d += blockDim.x)
        atomicAdd(dst + d, src[d] * scale);
}

__global__ void k_winmap(const int* __restrict__ ids, float* __restrict__ out2) {
    size_t i = (size_t)blockIdx.x * blockDim.x + threadIdx.x;
    size_t total = (size_t)NB * NT * NT;
    if (i >= total) return;
    int t = (int)(i % NT);
    size_t r = i / NT;
    int w = (int)(r % NT);
    int b = (int)(r / NT);
    out2[i] = (ids[b * NT + t] == w) ? 1.f : 0.f;
}

// ---------------- host orchestration ----------------------------------------
template<int EPI, int PREC>
static inline void launch_mma(const float* A, const float* B, float* C,
                              int M, int N, int K, int lda, int ldb, int ldc,
                              const int* ids, int zdim) {
    static bool attr_done = false;
    if (!attr_done) {
        cudaFuncSetAttribute(k_mma<EPI, PREC>,
                             cudaFuncAttributeMaxDynamicSharedMemorySize, MMA_SMEM_BYTES);
        attr_done = true;
    }
    dim3 grid(N / 128, M / 128, zdim);
    k_mma<EPI, PREC><<<grid, 256, MMA_SMEM_BYTES>>>(A, B, C, N, K, lda, ldb, ldc, ids);
}

template<int EPI>
static inline void launch_bb(const __nv_bfloat16* A, const __nv_bfloat16* Bt, void* C,
                             int M, int N, int K, int lda, int ldb, int ldc) {
    dim3 grid(N / 128, M / 128);
    k_mma_bb<EPI><<<grid, 256>>>(A, Bt, C, N, K, lda, ldb, ldc);
}

extern "C" void kernel_launch(void* const* d_in, const int* in_sizes, int n_in,
                              void* d_out, int out_size) {
    const float* x      = (const float*)d_in[0];
    const float* v_qkvw = (const float*)d_in[1];
    const float* v_outw = (const float*)d_in[2];
    const float* v_w1   = (const float*)d_in[3];
    const float* v_w2   = (const float*)d_in[4];
    const float* l_qkvw = (const float*)d_in[5];
    const float* l_outw = (const float*)d_in[6];
    const float* l_w1   = (const float*)d_in[7];
    const float* l_w2   = (const float*)d_in[8];

    float *qkv, *probs, *ctx, *tmp, *x1, *outv, *outl, *colsum, *wl, *wTq;
    __nv_bfloat16 *wbf, *ctxbf, *tmpbf, *x1bf, *outvbf;
    int* ids;
    cudaGetSymbolAddress((void**)&qkv,    g_qkv);
    cudaGetSymbolAddress((void**)&probs,  g_probs);
    cudaGetSymbolAddress((void**)&ctx,    g_ctx);
    cudaGetSymbolAddress((void**)&tmp,    g_tmp);
    cudaGetSymbolAddress((void**)&x1,     g_x1);
    cudaGetSymbolAddress((void**)&outv,   g_outv);
    cudaGetSymbolAddress((void**)&outl,   g_outl);
    cudaGetSymbolAddress((void**)&colsum, g_colsum);
    cudaGetSymbolAddress((void**)&ids,    g_ids);
    cudaGetSymbolAddress((void**)&wl,     g_wl);
    cudaGetSymbolAddress((void**)&wbf,    g_wTbf);
    cudaGetSymbolAddress((void**)&wTq,    g_wTq);
    cudaGetSymbolAddress((void**)&ctxbf,  g_ctxbf);
    cudaGetSymbolAddress((void**)&tmpbf,  g_tmpbf);
    cudaGetSymbolAddress((void**)&x1bf,   g_x1bf);
    cudaGetSymbolAddress((void**)&outvbf, g_outvbf);

    float* out = (float*)d_out;
    size_t sz1 = (size_t)NB * 2 * NT * ND;
    size_t szwm = (size_t)NB * NT * NT;

    // ---- weight transposes ----
    dim3 tb(32, 8);
    for (int c = 0; c < 3; c++)
        k_transpose<<<dim3(ND / 32, ND / 32), tb>>>(v_qkvw + (size_t)c * ND * ND,
                                                    wTq + (size_t)c * ND * ND, ND, ND);
    k_transpose_bf16<<<dim3(ND / 32, ND / 32), tb>>>(v_outw, wbf + WT_VOUT, ND, ND);
    k_transpose_bf16<<<dim3(NFF / 32, ND / 32), tb>>>(v_w1, wbf + WT_VW1, ND, NFF);
    k_transpose_bf16<<<dim3(ND / 32, NFF / 32), tb>>>(v_w2, wbf + WT_VW2, NFF, ND);
    for (int c = 0; c < 3; c++)
        k_transpose_bf16<<<dim3(ND / 32, ND / 32), tb>>>(l_qkvw + (size_t)c * ND * ND,
                                                         wbf + WT_LQKV + (size_t)c * ND * ND, ND, ND);
    k_transpose_bf16<<<dim3(ND / 32, ND / 32), tb>>>(l_outw, wbf + WT_LOUT, ND, ND);
    k_transpose_bf16<<<dim3(NFF / 32, ND / 32), tb>>>(l_w1, wbf + WT_LW1, ND, NFF);
    k_transpose_bf16<<<dim3(ND / 32, NFF / 32), tb>>>(l_w2, wbf + WT_LW2, NFF, ND);

    // ---- Layer 1 (vanilla). Mask-critical path in 3xTF32 ----
    for (int c = 0; c < 3; c++)
        launch_mma<0, 3>(x, wTq + (size_t)c * ND * ND, qkv + (size_t)c * NB * NT * ND,
                         MROWS, ND, ND, ND, ND, ND, nullptr, 1);
    launch_mma<2, 3>(qkv, qkv + (size_t)NB * NT * ND, probs,
                     NT, NT, NDH, ND, ND, NT, nullptr, NB * NH);
    k_zero<<<(NB * NT + 255) / 256, 256>>>(colsum, NB * NT);
    k_softmax_colsum<<<dim3(NT / 16, NB * NH), 256>>>(probs, colsum);
    k_mma_ctx<<<dim3(NT / 128, 1, NB * NH), 256>>>(probs, qkv, ctxbf);
    launch_bb<0>(ctxbf, wbf + WT_VOUT, tmp, MROWS, ND, ND, ND, ND, ND);
    k_add_ln<<<MROWS, 256>>>(x, tmp, x1, x1bf);
    launch_bb<2>(x1bf, wbf + WT_VW1, tmpbf, MROWS, NFF, ND, ND, ND, NFF);
    launch_bb<0>(tmpbf, wbf + WT_VW2, ctx, MROWS, ND, NFF, NFF, NFF, ND);
    k_add_ln<<<MROWS, 256>>>(x1, ctx, outv, outvbf);

    // ---- window ids (inputs computed at ~fp32 accuracy) ----
    k_windows<<<NB, 256>>>(colsum, ids);

    // ---- Layer 2 (windowed mask) ----
    for (int c = 0; c < 3; c++)
        launch_bb<0>(outvbf, wbf + WT_LQKV + (size_t)c * ND * ND,
                     qkv + (size_t)c * NB * NT * ND, MROWS, ND, ND, ND, ND, ND);
    launch_mma<2, 1>(qkv, qkv + (size_t)NB * NT * ND, probs,
                     NT, NT, NDH, ND, ND, NT, ids, NB * NH);
    k_zero<<<(NB * NT + 255) / 256, 256>>>(colsum, NB * NT);
    k_softmax_colsum<<<dim3(NT / 16, NB * NH), 256>>>(probs, colsum);
    k_mma_ctx<<<dim3(NT / 128, 1, NB * NH), 256>>>(probs, qkv, ctxbf);
    launch_bb<0>(ctxbf, wbf + WT_LOUT, tmp, MROWS, ND, ND, ND, ND, ND);
    k_add_ln<<<MROWS, 256>>>(outv, tmp, x1, x1bf);
    launch_bb<2>(x1bf, wbf + WT_LW1, tmpbf, MROWS, NFF, ND, ND, ND, NFF);
    launch_bb<0>(tmpbf, wbf + WT_LW2, ctx, MROWS, ND, NFF, NFF, NFF, ND);
    k_add_ln<<<MROWS, 256>>>(x1, ctx, outl, nullptr);

    k_softmax_vec<<<NB, 256>>>(colsum, wl);

    // ---- Assemble outputs ----
    if ((size_t)out_size >= sz1) {
        k_out_base<<<(int)((sz1 + 255) / 256), 256>>>(x, out);
        k_scatter<<<NB * NT, 128>>>(outl, wl, ids, out);
    }
    if ((size_t)out_size >= sz1 + szwm) {
        k_winmap<<<(int)((szwm + 255) / 256), 256>>>(ids, out + sz1);
    }
}

// round 15
// speedup vs baseline: 1.7960x; 1.0406x over previous
#include <cuda_runtime.h>
#include <cuda_bf16.h>
#include <math.h>
#include <cstdint>

// Problem constants
#define NB 8
#define NT 1024
#define ND 512
#define NFF 2048
#define NH 8
#define NDH 64
#define MROWS (NB*NT)   // 8192

// ---------------- scratch (device globals; no allocation allowed) -----------
__device__ float g_qkv[(size_t)3*NB*NT*ND];          // (3,b,t,d)
__device__ float g_probs[(size_t)NB*NH*NT*NT];       // fp32 scores (pre-softmax)
__device__ __nv_bfloat16 g_probsbf[(size_t)NB*NH*NT*NT];  // bf16 probs (post-softmax)
__device__ float g_ctx[(size_t)NB*NT*ND];            // fp32 (w2 output)
__device__ float g_tmp[(size_t)NB*NT*NFF];           // fp32 (out-proj output)
__device__ float g_x1[(size_t)NB*NT*ND];
__device__ float g_outv[(size_t)NB*NT*ND];
__device__ float g_outl[(size_t)NB*NT*ND];
__device__ float g_colsum[NB*NT];
__device__ int   g_ids[NB*NT];
__device__ float g_wl[NB*NT];
// bf16 activation copies
__device__ __nv_bfloat16 g_ctxbf[(size_t)NB*NT*ND];
__device__ __nv_bfloat16 g_tmpbf[(size_t)NB*NT*NFF];
__device__ __nv_bfloat16 g_x1bf[(size_t)NB*NT*ND];
__device__ __nv_bfloat16 g_outvbf[(size_t)NB*NT*ND];
// transposed bf16 weights
__device__ __nv_bfloat16 g_wTbf[5505024];
// transposed raw fp32 layer-1 qkv weights for 3xTF32 GEMM
__device__ float g_wTq[3*ND*ND];

#define WT_VOUT 0
#define WT_VW1  (WT_VOUT + ND*ND)
#define WT_VW2  (WT_VW1 + NFF*ND)
#define WT_LQKV (WT_VW2 + ND*NFF)
#define WT_LOUT (WT_LQKV + 3*ND*ND)
#define WT_LW1  (WT_LOUT + ND*ND)
#define WT_LW2  (WT_LW1 + NFF*ND)

// ==================== small PTX helpers =====================================
__device__ __forceinline__ uint32_t smem_u32(const void* p) {
    uint32_t a;
    asm("{ .reg .u64 t; cvta.to.shared.u64 t, %1; cvt.u32.u64 %0, t; }" : "=r"(a) : "l"(p));
    return a;
}
__device__ __forceinline__ void cp_async16(uint32_t s, const void* g) {
    asm volatile("cp.async.cg.shared.global [%0], [%1], 16;" :: "r"(s), "l"(g));
}
__device__ __forceinline__ uint32_t tf32u(float x) {
    uint32_t u;
    asm("cvt.rna.tf32.f32 %0, %1;" : "=r"(u) : "f"(x));
    return u;
}
__device__ __forceinline__ uint32_t bf16pack(float lo, float hi) {
    uint32_t r;
    asm("cvt.rn.bf16x2.f32 %0, %1, %2;" : "=r"(r) : "f"(hi), "f"(lo));
    return r;
}
__device__ __forceinline__ void mma_tf32(float* d, const uint32_t* a, uint32_t b0, uint32_t b1) {
    asm volatile(
        "mma.sync.aligned.m16n8k8.row.col.f32.tf32.tf32.f32 "
        "{%0,%1,%2,%3}, {%4,%5,%6,%7}, {%8,%9}, {%0,%1,%2,%3};"
        : "+f"(d[0]), "+f"(d[1]), "+f"(d[2]), "+f"(d[3])
        : "r"(a[0]), "r"(a[1]), "r"(a[2]), "r"(a[3]), "r"(b0), "r"(b1));
}
__device__ __forceinline__ void mma_bf16(float* d, const uint32_t* a, uint32_t b0, uint32_t b1) {
    asm volatile(
        "mma.sync.aligned.m16n8k16.row.col.f32.bf16.bf16.f32 "
        "{%0,%1,%2,%3}, {%4,%5,%6,%7}, {%8,%9}, {%0,%1,%2,%3};"
        : "+f"(d[0]), "+f"(d[1]), "+f"(d[2]), "+f"(d[3])
        : "r"(a[0]), "r"(a[1]), "r"(a[2]), "r"(a[3]), "r"(b0), "r"(b1));
}

#define MMA_PITCH 20
#define MMA_SMEM_BYTES (2 * 3 * 128 * MMA_PITCH * 4)   // 61440

// =================== tf32 mma GEMM (scores + layer-1 qkv) ===================
// C = A(MxK,lda) @ B(NxK,ldb)^T.  EPI: 0 plain, 2 scores (x0.125 + mask, z-batched)
// PREC: 1 tf32, 3 = 3xTF32 split (fp32-comparable).
template<int EPI, int PREC>
__global__ void __launch_bounds__(256) k_mma(const float* __restrict__ A,
                                             const float* __restrict__ B,
                                             float* __restrict__ C,
                                             int N, int K, int lda, int ldb, int ldc,
                                             const int* __restrict__ ids) {
    extern __shared__ float dsm[];
    float* sA = dsm;
    float* sB = dsm + 3 * 128 * MMA_PITCH;

    const int tid = threadIdx.x;
    const int wid = tid >> 5, lane = tid & 31;
    const int row0 = blockIdx.y * 128, col0 = blockIdx.x * 128;
    const int m_base = (wid & 3) * 32;
    const int n_base = (wid >> 2) * 64;
    const int g = lane >> 2, c = lane & 3;

    const float* Ap = A;
    const float* Bp = B;
    float* Cp = C;
    const int* idb = nullptr;
    if (EPI == 2) {
        int bb = blockIdx.z >> 3, hh = blockIdx.z & 7;
        size_t off = (size_t)bb * NT * ND + hh * NDH;
        Ap = A + off; Bp = B + off;
        Cp = C + (size_t)blockIdx.z * NT * NT;
        if (ids) idb = ids + bb * NT;
    }

    const uint32_t aS = smem_u32(sA);
    const uint32_t bS = smem_u32(sB);

    float acc[2][8][4];
    #pragma unroll
    for (int mt = 0; mt < 2; mt++)
        #pragma unroll
        for (int nt = 0; nt < 8; nt++)
            #pragma unroll
            for (int i = 0; i < 4; i++) acc[mt][nt][i] = 0.f;

    auto load_chunk = [&](int buf, int k0) {
        #pragma unroll
        for (int i = 0; i < 2; i++) {
            int q = tid + i * 256;
            int r = q >> 2, c4 = (q & 3) * 4;
            uint32_t soff = (uint32_t)((buf * 128 * MMA_PITCH + r * MMA_PITCH + c4) * 4);
            cp_async16(aS + soff, Ap + (size_t)(row0 + r) * lda + k0 + c4);
            cp_async16(bS + soff, Bp + (size_t)(col0 + r) * ldb + k0 + c4);
        }
        asm volatile("cp.async.commit_group;" ::: "memory");
    };

    const int nch = K >> 4;
    load_chunk(0, 0);
    if (nch > 1) load_chunk(1, 16);

    for (int ch = 0; ch < nch; ch++) {
        if (ch + 1 < nch) { asm volatile("cp.async.wait_group 1;" ::: "memory"); }
        else              { asm volatile("cp.async.wait_group 0;" ::: "memory"); }
        __syncthreads();
        if (ch + 2 < nch) load_chunk((ch + 2) % 3, (ch + 2) << 4);

        const float* pa = sA + (ch % 3) * 128 * MMA_PITCH;
        const float* pb = sB + (ch % 3) * 128 * MMA_PITCH;
        #pragma unroll
        for (int ks = 0; ks < 2; ks++) {
            const int k = ks * 8;
            uint32_t ahi[2][4], alo[2][4];
            #pragma unroll
            for (int mt = 0; mt < 2; mt++) {
                const float* ap = pa + (m_base + mt * 16 + g) * MMA_PITCH + k + c;
                float ar[4] = { ap[0], ap[8 * MMA_PITCH], ap[4], ap[8 * MMA_PITCH + 4] };
                #pragma unroll
                for (int j = 0; j < 4; j++) {
                    ahi[mt][j] = tf32u(ar[j]);
                    if (PREC == 3)
                        alo[mt][j] = tf32u(ar[j] - __uint_as_float(ahi[mt][j]));
                }
            }
            #pragma unroll
            for (int nt = 0; nt < 8; nt++) {
                const float* bp = pb + (n_base + nt * 8 + g) * MMA_PITCH + k + c;
                float br0 = bp[0], br1 = bp[4];
                uint32_t bhi0 = tf32u(br0), bhi1 = tf32u(br1);
                uint32_t blo0 = 0, blo1 = 0;
                if (PREC == 3) {
                    blo0 = tf32u(br0 - __uint_as_float(bhi0));
                    blo1 = tf32u(br1 - __uint_as_float(bhi1));
                }
                #pragma unroll
                for (int mt = 0; mt < 2; mt++) {
                    if (PREC == 3) {
                        mma_tf32(acc[mt][nt], ahi[mt], blo0, blo1);
                        mma_tf32(acc[mt][nt], alo[mt], bhi0, bhi1);
                    }
                    mma_tf32(acc[mt][nt], ahi[mt], bhi0, bhi1);
                }
            }
        }
        __syncthreads();
    }

    #pragma unroll
    for (int mt = 0; mt < 2; mt++) {
        int r = row0 + m_base + mt * 16 + g;
        int iq0 = 0, iq1 = 0;
        if (EPI == 2 && idb) { iq0 = idb[r]; iq1 = idb[r + 8]; }
        #pragma unroll
        for (int nt = 0; nt < 8; nt++) {
            int cc = col0 + n_base + nt * 8 + 2 * c;
            float* d = acc[mt][nt];
            if (EPI == 2) {
                d[0] *= 0.125f; d[1] *= 0.125f; d[2] *= 0.125f; d[3] *= 0.125f;
                if (idb) {
                    int ik0 = idb[cc], ik1 = idb[cc + 1];
                    if (iq0 != ik0) d[0] = -1e30f;
                    if (iq0 != ik1) d[1] = -1e30f;
                    if (iq1 != ik0) d[2] = -1e30f;
                    if (iq1 != ik1) d[3] = -1e30f;
                }
            }
            *reinterpret_cast<float2*>(Cp + (size_t)r * ldc + cc)       = make_float2(d[0], d[1]);
            *reinterpret_cast<float2*>(Cp + (size_t)(r + 8) * ldc + cc) = make_float2(d[2], d[3]);
        }
    }
}

// =================== bf16 x bf16 mma GEMM (weight GEMMs) ====================
// C = A(MxK bf16,lda) @ Bt(NxK bf16,ldb)^T, m16n8k16, BK=16, 3-stage.
// EPI: 0 fp32 out, 2 relu + bf16 out.
#define BPITCH 12
template<int EPI>
__global__ void __launch_bounds__(256) k_mma_bb(const __nv_bfloat16* __restrict__ A,
                                                const __nv_bfloat16* __restrict__ Bt,
                                                void* __restrict__ Cv,
                                                int N, int K, int lda, int ldb, int ldc) {
    __shared__ uint32_t sA[3][128 * BPITCH];
    __shared__ uint32_t sB[3][128 * BPITCH];

    const int tid = threadIdx.x;
    const int wid = tid >> 5, lane = tid & 31;
    const int row0 = blockIdx.y * 128, col0 = blockIdx.x * 128;
    const int m_base = (wid & 3) * 32;
    const int n_base = (wid >> 2) * 64;
    const int g = lane >> 2, c = lane & 3;

    const uint32_t aS = smem_u32(sA);
    const uint32_t bS = smem_u32(sB);

    float acc[2][8][4];
    #pragma unroll
    for (int mt = 0; mt < 2; mt++)
        #pragma unroll
        for (int nt = 0; nt < 8; nt++)
            #pragma unroll
            for (int i = 0; i < 4; i++) acc[mt][nt][i] = 0.f;

    auto load_chunk = [&](int buf, int k0) {
        int r = tid >> 1, half = tid & 1;
        uint32_t soff = (uint32_t)((buf * 128 * BPITCH + r * BPITCH + half * 4) * 4);
        cp_async16(aS + soff, A + (size_t)(row0 + r) * lda + k0 + half * 8);
        cp_async16(bS + soff, Bt + (size_t)(col0 + r) * ldb + k0 + half * 8);
        asm volatile("cp.async.commit_group;" ::: "memory");
    };

    const int nch = K >> 4;
    load_chunk(0, 0);
    if (nch > 1) load_chunk(1, 16);

    for (int ch = 0; ch < nch; ch++) {
        if (ch + 1 < nch) { asm volatile("cp.async.wait_group 1;" ::: "memory"); }
        else              { asm volatile("cp.async.wait_group 0;" ::: "memory"); }
        __syncthreads();
        if (ch + 2 < nch) load_chunk((ch + 2) % 3, (ch + 2) << 4);

        const uint32_t* pa = sA[ch % 3];
        const uint32_t* pb = sB[ch % 3];

        uint32_t afr[2][4];
        #pragma unroll
        for (int mt = 0; mt < 2; mt++) {
            const uint32_t* ap = pa + (m_base + mt * 16 + g) * BPITCH + c;
            afr[mt][0] = ap[0];
            afr[mt][1] = ap[8 * BPITCH];
            afr[mt][2] = ap[4];
            afr[mt][3] = ap[8 * BPITCH + 4];
        }
        #pragma unroll
        for (int nt = 0; nt < 8; nt++) {
            const uint32_t* bp = pb + (n_base + nt * 8 + g) * BPITCH + c;
            uint32_t b0 = bp[0], b1 = bp[4];
            #pragma unroll
            for (int mt = 0; mt < 2; mt++)
                mma_bf16(acc[mt][nt], afr[mt], b0, b1);
        }
        __syncthreads();
    }

    #pragma unroll
    for (int mt = 0; mt < 2; mt++) {
        int r = row0 + m_base + mt * 16 + g;
        #pragma unroll
        for (int nt = 0; nt < 8; nt++) {
            int cc = col0 + n_base + nt * 8 + 2 * c;
            float* d = acc[mt][nt];
            if (EPI == 0) {
                float* C = (float*)Cv;
                *reinterpret_cast<float2*>(C + (size_t)r * ldc + cc)       = make_float2(d[0], d[1]);
                *reinterpret_cast<float2*>(C + (size_t)(r + 8) * ldc + cc) = make_float2(d[2], d[3]);
            } else {
                d[0] = fmaxf(d[0], 0.f); d[1] = fmaxf(d[1], 0.f);
                d[2] = fmaxf(d[2], 0.f); d[3] = fmaxf(d[3], 0.f);
                __nv_bfloat16* Cb = (__nv_bfloat16*)Cv;
                *reinterpret_cast<uint32_t*>(Cb + (size_t)r * ldc + cc)       = bf16pack(d[0], d[1]);
                *reinterpret_cast<uint32_t*>(Cb + (size_t)(r + 8) * ldc + cc) = bf16pack(d[2], d[3]);
            }
        }
    }
}

// =================== ctx mma (bf16 probs): C[q,d] = sum_k P[q,k] V[k,d] =====
// P bf16 (post-softmax), V fp32 packed to bf16 at fragment time; m16n8k16.
#define VPITCH 72
__global__ void __launch_bounds__(256) k_mma_ctx(const __nv_bfloat16* __restrict__ P,
                                                 const float* __restrict__ qkv,
                                                 __nv_bfloat16* __restrict__ C) {
    __shared__ uint32_t sP[3][128 * BPITCH];
    __shared__ float    sV[3][16 * VPITCH];

    const int tid = threadIdx.x;
    const int wid = tid >> 5, lane = tid & 31;
    const int z = blockIdx.z;
    const int b = z >> 3, h = z & 7;
    const int row0 = blockIdx.x * 128;
    const int m_base = (wid & 3) * 32;
    const int n_base = (wid >> 2) * 32;
    const int g = lane >> 2, c = lane & 3;

    const __nv_bfloat16* Ap = P + (size_t)z * NT * NT;
    const float* Vp = qkv + (size_t)(2 * NB + b) * NT * ND + h * NDH;
    __nv_bfloat16* Cp = C + (size_t)b * NT * ND + h * NDH;

    const uint32_t pS = smem_u32(sP);
    const uint32_t vS = smem_u32(sV);

    float acc[2][4][4];
    #pragma unroll
    for (int mt = 0; mt < 2; mt++)
        #pragma unroll
        for (int nt = 0; nt < 4; nt++)
            #pragma unroll
            for (int i = 0; i < 4; i++) acc[mt][nt][i] = 0.f;

    auto load_chunk = [&](int buf, int k0) {
        {
            int r = tid >> 1, half = tid & 1;
            uint32_t soff = (uint32_t)((buf * 128 * BPITCH + r * BPITCH + half * 4) * 4);
            cp_async16(pS + soff, Ap + (size_t)(row0 + r) * NT + k0 + half * 8);
        }
        {
            int r = tid >> 4, c4 = (tid & 15) * 4;
            uint32_t soff = (uint32_t)((buf * 16 * VPITCH + r * VPITCH + c4) * 4);
            cp_async16(vS + soff, Vp + (size_t)(k0 + r) * ND + c4);
        }
        asm volatile("cp.async.commit_group;" ::: "memory");
    };

    const int nch = NT >> 4;   // 64
    load_chunk(0, 0);
    load_chunk(1, 16);

    for (int ch = 0; ch < nch; ch++) {
        if (ch + 1 < nch) { asm volatile("cp.async.wait_group 1;" ::: "memory"); }
        else              { asm volatile("cp.async.wait_group 0;" ::: "memory"); }
        __syncthreads();
        if (ch + 2 < nch) load_chunk((ch + 2) % 3, (ch + 2) << 4);

        const uint32_t* pa = sP[ch % 3];
        const float*    pv = sV[ch % 3];

        uint32_t afr[2][4];
        #pragma unroll
        for (int mt = 0; mt < 2; mt++) {
            const uint32_t* ap = pa + (m_base + mt * 16 + g) * BPITCH + c;
            afr[mt][0] = ap[0];
            afr[mt][1] = ap[8 * BPITCH];
            afr[mt][2] = ap[4];
            afr[mt][3] = ap[8 * BPITCH + 4];
        }
        #pragma unroll
        for (int nt = 0; nt < 4; nt++) {
            int n = n_base + nt * 8 + g;
            uint32_t b0 = bf16pack(pv[(2 * c) * VPITCH + n],     pv[(2 * c + 1) * VPITCH + n]);
            uint32_t b1 = bf16pack(pv[(8 + 2 * c) * VPITCH + n], pv[(9 + 2 * c) * VPITCH + n]);
            #pragma unroll
            for (int mt = 0; mt < 2; mt++)
                mma_bf16(acc[mt][nt], afr[mt], b0, b1);
        }
        __syncthreads();
    }

    #pragma unroll
    for (int mt = 0; mt < 2; mt++) {
        int r = row0 + m_base + mt * 16 + g;
        #pragma unroll
        for (int nt = 0; nt < 4; nt++) {
            int cc = n_base + nt * 8 + 2 * c;
            float* d = acc[mt][nt];
            *reinterpret_cast<uint32_t*>(Cp + (size_t)r * ND + cc)       = bf16pack(d[0], d[1]);
            *reinterpret_cast<uint32_t*>(Cp + (size_t)(r + 8) * ND + cc) = bf16pack(d[2], d[3]);
        }
    }
}

// ---------------- weight transposes -----------------------------------------
__global__ void k_transpose(const float* __restrict__ B, float* __restrict__ Bt,
                            int K, int N) {
    __shared__ float t[32][33];
    int n0 = blockIdx.x * 32, k0 = blockIdx.y * 32;
    int tx = threadIdx.x, ty = threadIdx.y;
    #pragma unroll
    for (int i = 0; i < 4; i++)
        t[ty + i * 8][tx] = B[(size_t)(k0 + ty + i * 8) * N + n0 + tx];
    __syncthreads();
    #pragma unroll
    for (int i = 0; i < 4; i++)
        Bt[(size_t)(n0 + ty + i * 8) * K + k0 + tx] = t[tx][ty + i * 8];
}

__global__ void k_transpose_bf16(const float* __restrict__ B, __nv_bfloat16* __restrict__ Bt,
                                 int K, int N) {
    __shared__ float t[32][33];
    int n0 = blockIdx.x * 32, k0 = blockIdx.y * 32;
    int tx = threadIdx.x, ty = threadIdx.y;
    #pragma unroll
    for (int i = 0; i < 4; i++)
        t[ty + i * 8][tx] = B[(size_t)(k0 + ty + i * 8) * N + n0 + tx];
    __syncthreads();
    #pragma unroll
    for (int i = 0; i < 4; i++)
        Bt[(size_t)(n0 + ty + i * 8) * K + k0 + tx] = __float2bfloat16(t[tx][ty + i * 8]);
}

// ---------- fused row softmax + colsum; fp32 in, bf16 probs out --------------
// grid: (NT/16, NB*NH), block 256 (8 warps, 2 rows each).
// colsum accumulated from the fp32 normalized values (mask path untouched).
__global__ void __launch_bounds__(256) k_softmax_colsum(const float* __restrict__ P,
                                                        __nv_bfloat16* __restrict__ Pbf,
                                                        float* __restrict__ colsum) {
    const int z = blockIdx.y;
    const int b = z >> 3;
    const int row0 = blockIdx.x * 16;
    const int tid = threadIdx.x;
    const int wid = tid >> 5, lane = tid & 31;

    __shared__ float scol[NT];
    for (int i = tid; i < NT; i += 256) scol[i] = 0.f;
    __syncthreads();

    float4 accc[8];
    #pragma unroll
    for (int j = 0; j < 8; j++) accc[j] = make_float4(0.f, 0.f, 0.f, 0.f);

    #pragma unroll
    for (int rr = 0; rr < 2; rr++) {
        int r = row0 + wid * 2 + rr;
        const float4* p = reinterpret_cast<const float4*>(P + ((size_t)z * NT + r) * NT);
        uint2* pb = reinterpret_cast<uint2*>(Pbf + ((size_t)z * NT + r) * NT);
        float4 v[8];
        float m = -1e30f;
        #pragma unroll
        for (int j = 0; j < 8; j++) {
            v[j] = p[j * 32 + lane];
            m = fmaxf(m, fmaxf(fmaxf(v[j].x, v[j].y), fmaxf(v[j].z, v[j].w)));
        }
        #pragma unroll
        for (int o = 16; o > 0; o >>= 1) m = fmaxf(m, __shfl_xor_sync(0xFFFFFFFFu, m, o));
        float s = 0.f;
        #pragma unroll
        for (int j = 0; j < 8; j++) {
            v[j].x = __expf(v[j].x - m); v[j].y = __expf(v[j].y - m);
            v[j].z = __expf(v[j].z - m); v[j].w = __expf(v[j].w - m);
            s += v[j].x + v[j].y + v[j].z + v[j].w;
        }
        #pragma unroll
        for (int o = 16; o > 0; o >>= 1) s += __shfl_xor_sync(0xFFFFFFFFu, s, o);
        float inv = 1.f / s;
        #pragma unroll
        for (int j = 0; j < 8; j++) {
            v[j].x *= inv; v[j].y *= inv; v[j].z *= inv; v[j].w *= inv;
            uint2 w2;
            w2.x = bf16pack(v[j].x, v[j].y);
            w2.y = bf16pack(v[j].z, v[j].w);
            pb[j * 32 + lane] = w2;
            accc[j].x += v[j].x; accc[j].y += v[j].y;
            accc[j].z += v[j].z; accc[j].w += v[j].w;
        }
    }

    #pragma unroll
    for (int j = 0; j < 8; j++) {
        int cb = (j * 32 + lane) * 4;
        atomicAdd(&scol[cb + 0], accc[j].x);
        atomicAdd(&scol[cb + 1], accc[j].y);
        atomicAdd(&scol[cb + 2], accc[j].z);
        atomicAdd(&scol[cb + 3], accc[j].w);
    }
    __syncthreads();
    for (int i = tid; i < NT; i += 256)
        atomicAdd(&colsum[b * NT + i], scol[i] * (1.f / NH));
}

__global__ void k_zero(float* p, int n) {
    int i = blockIdx.x * blockDim.x + threadIdx.x;
    if (i < n) p[i] = 0.f;
}

// ---------------- residual add + layernorm (dual fp32/bf16 output) ----------
__global__ void k_add_ln(const float* __restrict__ X, const float* __restrict__ Y,
                         float* __restrict__ O, __nv_bfloat16* __restrict__ Obf) {
    int row = blockIdx.x;
    const float* x = X + (size_t)row * ND;
    const float* y = Y + (size_t)row * ND;
    __shared__ float s[ND];
    __shared__ float red[256];
    int tid = threadIdx.x;
    float lsum = 0.f;
    for (int i = tid; i < ND; i += 256) { float v = x[i] + y[i]; s[i] = v; lsum += v; }
    red[tid] = lsum; __syncthreads();
    for (int o = 128; o > 0; o >>= 1) { if (tid < o) red[tid] += red[tid + o]; __syncthreads(); }
    float mean = red[0] * (1.f / ND); __syncthreads();
    float lv = 0.f;
    for (int i = tid; i < ND; i += 256) { float d = s[i] - mean; lv += d * d; }
    red[tid] = lv; __syncthreads();
    for (int o = 128; o > 0; o >>= 1) { if (tid < o) red[tid] += red[tid + o]; __syncthreads(); }
    float inv = rsqrtf(red[0] * (1.f / ND) + 1e-5f);
    for (int i = tid; i < ND; i += 256) {
        float v = (s[i] - mean) * inv;
        O[(size_t)row * ND + i] = v;
        if (Obf) Obf[(size_t)row * ND + i] = __float2bfloat16(v);
    }
}

// ---------------- window ids ------------------------------------------------
__global__ void k_windows(const float* __restrict__ colsum, int* __restrict__ ids) {
    int b = blockIdx.x;
    const float* w = colsum + b * NT;
    __shared__ float r1[256], r2[256];
    __shared__ unsigned char wb[NT];
    int tid = threadIdx.x;
    float mn = 1e30f, mx = -1e30f;
    for (int i = tid; i < NT; i += 256) { float v = w[i]; mn = fminf(mn, v); mx = fmaxf(mx, v); }
    r1[tid] = mn; r2[tid] = mx; __syncthreads();
    for (int o = 128; o > 0; o >>= 1) {
        if (tid < o) { r1[tid] = fminf(r1[tid], r1[tid + o]); r2[tid] = fmaxf(r2[tid], r2[tid + o]); }
        __syncthreads();
    }
    float wmin = r1[0];
    float denom = r2[0] - r1[0] + 1e-8f;
    for (int i = tid; i < NT; i += 256)
        wb[i] = ((w[i] - wmin) / denom >= 0.5f) ? 1 : 0;
    __syncthreads();
    if (tid == 0) {
        int* o = ids + b * NT;
        int cur = wb[0], start = 0, wid = 0;
        o[0] = 0;
        for (int t = 1; t < NT; t++) {
            int wt = wb[t];
            if (wt != cur) {
                if (start + 1 == t) { cur = wt; }
                else { cur = wt; start = t; wid++; }
            }
            o[t] = wid;
        }
    }
}

// ---------------- per-batch softmax over T (for wl) -------------------------
__global__ void k_softmax_vec(const float* __restrict__ in, float* __restrict__ out) {
    int b = blockIdx.x;
    const float* p = in + b * NT;
    float* q = out + b * NT;
    __shared__ float red[256];
    int tid = threadIdx.x;
    float v[4];
    float m = -1e30f;
    #pragma unroll
    for (int i = 0; i < 4; i++) { v[i] = p[tid + i * 256]; m = fmaxf(m, v[i]); }
    red[tid] = m; __syncthreads();
    for (int o = 128; o > 0; o >>= 1) { if (tid < o) red[tid] = fmaxf(red[tid], red[tid + o]); __syncthreads(); }
    m = red[0]; __syncthreads();
    float s = 0.f;
    #pragma unroll
    for (int i = 0; i < 4; i++) { v[i] = __expf(v[i] - m); s += v[i]; }
    red[tid] = s; __syncthreads();
    for (int o = 128; o > 0; o >>= 1) { if (tid < o) red[tid] += red[tid + o]; __syncthreads(); }
    float inv = 1.f / red[0];
    #pragma unroll
    for (int i = 0; i < 4; i++) q[tid + i * 256] = v[i] * inv;
}

// ---------------- output assembly -------------------------------------------
__global__ void k_out_base(const float* __restrict__ x, float* __restrict__ out) {
    size_t i = (size_t)blockIdx.x * blockDim.x + threadIdx.x;
    size_t total = (size_t)NB * 2 * NT * ND;
    if (i >= total) return;
    int d = (int)(i % ND);
    size_t r = i / ND;
    int row = (int)(r % (2 * NT));
    int b = (int)(r / (2 * NT));
    out[i] = (row < NT) ? 0.f : x[((size_t)b * NT + (row - NT)) * ND + d];
}

__global__ void k_scatter(const float* __restrict__ outl, const float* __restrict__ wl,
                          const int* __restrict__ ids, float* __restrict__ out) {
    int bt = blockIdx.x; int b = bt / NT;
    int w = ids[bt];
    float scale = wl[bt];
    float* dst = out + ((size_t)b * 2 * NT + w) * ND;
    const float* src = outl + (size_t)bt * ND;
    for (int d = threadIdx.x; d < ND; d += blockDim.x)
        atomicAdd(dst + d, src[d] * scale);
}

__global__ void k_winmap(const int* __restrict__ ids, float* __restrict__ out2) {
    size_t i = (size_t)blockIdx.x * blockDim.x + threadIdx.x;
    size_t total = (size_t)NB * NT * NT;
    if (i >= total) return;
    int t = (int)(i % NT);
    size_t r = i / NT;
    int w = (int)(r % NT);
    int b = (int)(r / NT);
    out2[i] = (ids[b * NT + t] == w) ? 1.f : 0.f;
}

// ---------------- host orchestration ----------------------------------------
template<int EPI, int PREC>
static inline void launch_mma(const float* A, const float* B, float* C,
                              int M, int N, int K, int lda, int ldb, int ldc,
                              const int* ids, int zdim) {
    static bool attr_done = false;
    if (!attr_done) {
        cudaFuncSetAttribute(k_mma<EPI, PREC>,
                             cudaFuncAttributeMaxDynamicSharedMemorySize, MMA_SMEM_BYTES);
        attr_done = true;
    }
    dim3 grid(N / 128, M / 128, zdim);
    k_mma<EPI, PREC><<<grid, 256, MMA_SMEM_BYTES>>>(A, B, C, N, K, lda, ldb, ldc, ids);
}

template<int EPI>
static inline void launch_bb(const __nv_bfloat16* A, const __nv_bfloat16* Bt, void* C,
                             int M, int N, int K, int lda, int ldb, int ldc) {
    dim3 grid(N / 128, M / 128);
    k_mma_bb<EPI><<<grid, 256>>>(A, Bt, C, N, K, lda, ldb, ldc);
}

extern "C" void kernel_launch(void* const* d_in, const int* in_sizes, int n_in,
                              void* d_out, int out_size) {
    const float* x      = (const float*)d_in[0];
    const float* v_qkvw = (const float*)d_in[1];
    const float* v_outw = (const float*)d_in[2];
    const float* v_w1   = (const float*)d_in[3];
    const float* v_w2   = (const float*)d_in[4];
    const float* l_qkvw = (const float*)d_in[5];
    const float* l_outw = (const float*)d_in[6];
    const float* l_w1   = (const float*)d_in[7];
    const float* l_w2   = (const float*)d_in[8];

    float *qkv, *probs, *ctx, *tmp, *x1, *outv, *outl, *colsum, *wl, *wTq;
    __nv_bfloat16 *probsbf, *wbf, *ctxbf, *tmpbf, *x1bf, *outvbf;
    int* ids;
    cudaGetSymbolAddress((void**)&qkv,     g_qkv);
    cudaGetSymbolAddress((void**)&probs,   g_probs);
    cudaGetSymbolAddress((void**)&probsbf, g_probsbf);
    cudaGetSymbolAddress((void**)&ctx,     g_ctx);
    cudaGetSymbolAddress((void**)&tmp,     g_tmp);
    cudaGetSymbolAddress((void**)&x1,      g_x1);
    cudaGetSymbolAddress((void**)&outv,    g_outv);
    cudaGetSymbolAddress((void**)&outl,    g_outl);
    cudaGetSymbolAddress((void**)&colsum,  g_colsum);
    cudaGetSymbolAddress((void**)&ids,     g_ids);
    cudaGetSymbolAddress((void**)&wl,      g_wl);
    cudaGetSymbolAddress((void**)&wbf,     g_wTbf);
    cudaGetSymbolAddress((void**)&wTq,     g_wTq);
    cudaGetSymbolAddress((void**)&ctxbf,   g_ctxbf);
    cudaGetSymbolAddress((void**)&tmpbf,   g_tmpbf);
    cudaGetSymbolAddress((void**)&x1bf,    g_x1bf);
    cudaGetSymbolAddress((void**)&outvbf,  g_outvbf);

    float* out = (float*)d_out;
    size_t sz1 = (size_t)NB * 2 * NT * ND;
    size_t szwm = (size_t)NB * NT * NT;

    // ---- weight transposes ----
    dim3 tb(32, 8);
    for (int c = 0; c < 3; c++)
        k_transpose<<<dim3(ND / 32, ND / 32), tb>>>(v_qkvw + (size_t)c * ND * ND,
                                                    wTq + (size_t)c * ND * ND, ND, ND);
    k_transpose_bf16<<<dim3(ND / 32, ND / 32), tb>>>(v_outw, wbf + WT_VOUT, ND, ND);
    k_transpose_bf16<<<dim3(NFF / 32, ND / 32), tb>>>(v_w1, wbf + WT_VW1, ND, NFF);
    k_transpose_bf16<<<dim3(ND / 32, NFF / 32), tb>>>(v_w2, wbf + WT_VW2, NFF, ND);
    for (int c = 0; c < 3; c++)
        k_transpose_bf16<<<dim3(ND / 32, ND / 32), tb>>>(l_qkvw + (size_t)c * ND * ND,
                                                         wbf + WT_LQKV + (size_t)c * ND * ND, ND, ND);
    k_transpose_bf16<<<dim3(ND / 32, ND / 32), tb>>>(l_outw, wbf + WT_LOUT, ND, ND);
    k_transpose_bf16<<<dim3(NFF / 32, ND / 32), tb>>>(l_w1, wbf + WT_LW1, ND, NFF);
    k_transpose_bf16<<<dim3(ND / 32, NFF / 32), tb>>>(l_w2, wbf + WT_LW2, NFF, ND);

    // ---- Layer 1 (vanilla). Mask-critical path in 3xTF32 ----
    for (int c = 0; c < 3; c++)
        launch_mma<0, 3>(x, wTq + (size_t)c * ND * ND, qkv + (size_t)c * NB * NT * ND,
                         MROWS, ND, ND, ND, ND, ND, nullptr, 1);
    launch_mma<2, 3>(qkv, qkv + (size_t)NB * NT * ND, probs,
                     NT, NT, NDH, ND, ND, NT, nullptr, NB * NH);
    k_zero<<<(NB * NT + 255) / 256, 256>>>(colsum, NB * NT);
    k_softmax_colsum<<<dim3(NT / 16, NB * NH), 256>>>(probs, probsbf, colsum);
    k_mma_ctx<<<dim3(NT / 128, 1, NB * NH), 256>>>(probsbf, qkv, ctxbf);
    launch_bb<0>(ctxbf, wbf + WT_VOUT, tmp, MROWS, ND, ND, ND, ND, ND);
    k_add_ln<<<MROWS, 256>>>(x, tmp, x1, x1bf);
    launch_bb<2>(x1bf, wbf + WT_VW1, tmpbf, MROWS, NFF, ND, ND, ND, NFF);
    launch_bb<0>(tmpbf, wbf + WT_VW2, ctx, MROWS, ND, NFF, NFF, NFF, ND);
    k_add_ln<<<MROWS, 256>>>(x1, ctx, outv, outvbf);

    // ---- window ids (colsum computed from fp32 softmax values) ----
    k_windows<<<NB, 256>>>(colsum, ids);

    // ---- Layer 2 (windowed mask) ----
    for (int c = 0; c < 3; c++)
        launch_bb<0>(outvbf, wbf + WT_LQKV + (size_t)c * ND * ND,
                     qkv + (size_t)c * NB * NT * ND, MROWS, ND, ND, ND, ND, ND);
    launch_mma<2, 1>(qkv, qkv + (size_t)NB * NT * ND, probs,
                     NT, NT, NDH, ND, ND, NT, ids, NB * NH);
    k_zero<<<(NB * NT + 255) / 256, 256>>>(colsum, NB * NT);
    k_softmax_colsum<<<dim3(NT / 16, NB * NH), 256>>>(probs, probsbf, colsum);
    k_mma_ctx<<<dim3(NT / 128, 1, NB * NH), 256>>>(probsbf, qkv, ctxbf);
    launch_bb<0>(ctxbf, wbf + WT_LOUT, tmp, MROWS, ND, ND, ND, ND, ND);
    k_add_ln<<<MROWS, 256>>>(outv, tmp, x1, x1bf);
    launch_bb<2>(x1bf, wbf + WT_LW1, tmpbf, MROWS, NFF, ND, ND, ND, NFF);
    launch_bb<0>(tmpbf, wbf + WT_LW2, ctx, MROWS, ND, NFF, NFF, NFF, ND);
    k_add_ln<<<MROWS, 256>>>(x1, ctx, outl, nullptr);

    k_softmax_vec<<<NB, 256>>>(colsum, wl);

    // ---- Assemble outputs ----
    if ((size_t)out_size >= sz1) {
        k_out_base<<<(int)((sz1 + 255) / 256), 256>>>(x, out);
        k_scatter<<<NB * NT, 128>>>(outl, wl, ids, out);
    }
    if ((size_t)out_size >= sz1 + szwm) {
        k_winmap<<<(int)((szwm + 255) / 256), 256>>>(ids, out + sz1);
    }
}